// round 9
// baseline (speedup 1.0000x reference)
#include <cuda_runtime.h>
#include <cuda_bf16.h>
#include <math.h>
#include <cstdint>

#define N_NODES 50000
#define N_EDGES 800000

// ================= scratch =================
__device__ int   g_is64;
__device__ int   g_src[N_EDGES];
__device__ int   g_dst[N_EDGES];
__device__ int   g_edeg[N_NODES];
__device__ float g_dinv[N_NODES];
__device__ int   g_rowptr[N_NODES + 1];
__device__ int   g_cursor[N_NODES];
__device__ int   g_col[N_EDGES];
__device__ float g_wedge[N_EDGES];

__device__ float g_bufA[N_NODES * 256];   // [h_s1 | h2a] fp32 (feeds agg256)
__device__ float g_h1[N_NODES * 128];
__device__ float g_h2[N_NODES * 128];

// bf16 split operands (plain row-major)
__device__ __nv_bfloat16 g_aggxh[N_NODES * 128];
__device__ __nv_bfloat16 g_aggxl[N_NODES * 128];
__device__ __nv_bfloat16 g_agg2h[N_NODES * 256];
__device__ __nv_bfloat16 g_agg2l[N_NODES * 256];
__device__ __nv_bfloat16 g_combh[N_NODES * 256];  // [h_struct | h_meta] split
__device__ __nv_bfloat16 g_combl[N_NODES * 256];
__device__ __nv_bfloat16 g_wth[6][16384];
__device__ __nv_bfloat16 g_wtl[6][16384];

// ================= helpers =================
__device__ __forceinline__ uint32_t smem_u32(const void* p) {
    uint32_t a;
    asm("{ .reg .u64 t; cvta.to.shared.u64 t, %1; cvt.u32.u64 %0, t; }" : "=r"(a) : "l"(p));
    return a;
}
__device__ __forceinline__ void ldsm_x4(uint32_t* r, uint32_t addr) {
    asm volatile("ldmatrix.sync.aligned.m8n8.x4.shared.b16 {%0,%1,%2,%3}, [%4];"
                 : "=r"(r[0]), "=r"(r[1]), "=r"(r[2]), "=r"(r[3]) : "r"(addr));
}
__device__ __forceinline__ void ldsm_x2(uint32_t* r, uint32_t addr) {
    asm volatile("ldmatrix.sync.aligned.m8n8.x2.shared.b16 {%0,%1}, [%2];"
                 : "=r"(r[0]), "=r"(r[1]) : "r"(addr));
}
__device__ __forceinline__ void mma_bf16(float* d, const uint32_t* a, const uint32_t* b) {
    asm volatile("mma.sync.aligned.m16n8k16.row.col.f32.bf16.bf16.f32 "
                 "{%0,%1,%2,%3}, {%4,%5,%6,%7}, {%8,%9}, {%0,%1,%2,%3};"
                 : "+f"(d[0]), "+f"(d[1]), "+f"(d[2]), "+f"(d[3])
                 : "r"(a[0]), "r"(a[1]), "r"(a[2]), "r"(a[3]), "r"(b[0]), "r"(b[1]));
}
__device__ __forceinline__ void split_bf16(float v, __nv_bfloat16& h, __nv_bfloat16& l) {
    __nv_bfloat16 hb = __float2bfloat16(v);
    h = hb;
    l = __float2bfloat16(v - __bfloat162float(hb));
}

// ================= fused detect + edeg zero =================
__global__ void k_detect_init(const int* __restrict__ ei32) {
    int i = blockIdx.x * blockDim.x + threadIdx.x;
    if (i < N_NODES) g_edeg[i] = 0;
    if (blockIdx.x == 0) {
        __shared__ int nz;
        if (threadIdx.x == 0) nz = 0;
        __syncthreads();
        int local = 0;
        for (int q = threadIdx.x; q < 2048; q += blockDim.x)
            if (ei32[2 * q + 1] != 0) local = 1;
        if (local) atomicOr(&nz, 1);
        __syncthreads();
        if (threadIdx.x == 0) g_is64 = nz ? 0 : 1;
    }
}

// ================= fused extract + count =================
__global__ void k_extract_count(const int* __restrict__ ei32) {
    int e = blockIdx.x * blockDim.x + threadIdx.x;
    if (e < N_EDGES) {
        int s, d;
        if (g_is64) { s = ei32[2 * e]; d = ei32[2 * (N_EDGES + e)]; }
        else        { s = ei32[e];     d = ei32[N_EDGES + e]; }
        g_src[e] = s; g_dst[e] = d;
        atomicAdd(&g_edeg[d], 1);
    }
}

// ================= fused scan + dinv =================
__global__ void k_scan_dinv() {
    __shared__ int part[1024];
    const int t = threadIdx.x;
    const int CH = (N_NODES + 1023) / 1024;
    int start = t * CH;
    int s = 0;
    for (int i = 0; i < CH; i++) { int idx = start + i; if (idx < N_NODES) s += g_edeg[idx]; }
    part[t] = s;
    __syncthreads();
    for (int off = 1; off < 1024; off <<= 1) {
        int v = (t >= off) ? part[t - off] : 0;
        __syncthreads();
        part[t] += v;
        __syncthreads();
    }
    int run = (t == 0) ? 0 : part[t - 1];
    for (int i = 0; i < CH; i++) {
        int idx = start + i;
        if (idx < N_NODES) {
            g_rowptr[idx] = run;
            g_cursor[idx] = run;
            g_dinv[idx] = rsqrtf((float)(g_edeg[idx] + 1));
            run += g_edeg[idx];
        }
    }
    if (t == 1023) g_rowptr[N_NODES] = run;
}

__global__ void k_fill() {
    int e = blockIdx.x * blockDim.x + threadIdx.x;
    if (e < N_EDGES) {
        int s = g_src[e], d = g_dst[e];
        int p = atomicAdd(&g_cursor[d], 1);
        g_col[p] = s;
        g_wedge[p] = g_dinv[s] * g_dinv[d];
    }
}

// weights -> transposed split: Wt[n][k] from W[k][n]
struct PrepB { const float* W[6]; int K[6]; int N[6]; };
__global__ void k_prepB(PrepB p) {
    int b = blockIdx.x;
    const float* W = p.W[b];
    int K = p.K[b], N = p.N[b];
    for (int idx = threadIdx.x; idx < K * N; idx += blockDim.x) {
        int k = idx / N, n = idx % N;
        split_bf16(W[idx], g_wth[b][n * K + k], g_wtl[b][n * K + k]);
    }
}

// ================= warp-per-node aggregation =================
__global__ __launch_bounds__(256, 8) void k_agg128(const float* __restrict__ in,
                         __nv_bfloat16* __restrict__ oh, __nv_bfloat16* __restrict__ ol) {
    const int warp = threadIdx.x >> 5, lane = threadIdx.x & 31;
    const int n = blockIdx.x * 8 + warp;
    const int c4 = lane * 4;
    float dn = g_dinv[n];
    float4 self = *reinterpret_cast<const float4*>(in + (size_t)n * 128 + c4);
    float4 acc;
    acc.x = dn * dn * self.x; acc.y = dn * dn * self.y;
    acc.z = dn * dn * self.z; acc.w = dn * dn * self.w;
    const int beg = g_rowptr[n], end = g_rowptr[n + 1];
    for (int base = beg; base < end; base += 32) {
        int cnt = end - base; if (cnt > 32) cnt = 32;
        int   col = 0; float wt = 0.0f;
        if (lane < cnt) { col = g_col[base + lane]; wt = g_wedge[base + lane]; }
        for (int j = 0; j < cnt; j++) {
            int   idx = __shfl_sync(0xFFFFFFFFu, col, j);
            float ww  = __shfl_sync(0xFFFFFFFFu, wt,  j);
            float4 v = *reinterpret_cast<const float4*>(in + (size_t)idx * 128 + c4);
            acc.x += ww * v.x; acc.y += ww * v.y; acc.z += ww * v.z; acc.w += ww * v.w;
        }
    }
    __nv_bfloat16 h0, l0, h1, l1, h2, l2, h3, l3;
    split_bf16(acc.x, h0, l0); split_bf16(acc.y, h1, l1);
    split_bf16(acc.z, h2, l2); split_bf16(acc.w, h3, l3);
    *reinterpret_cast<__nv_bfloat162*>(oh + (size_t)n * 128 + c4)     = __nv_bfloat162{h0, h1};
    *reinterpret_cast<__nv_bfloat162*>(oh + (size_t)n * 128 + c4 + 2) = __nv_bfloat162{h2, h3};
    *reinterpret_cast<__nv_bfloat162*>(ol + (size_t)n * 128 + c4)     = __nv_bfloat162{l0, l1};
    *reinterpret_cast<__nv_bfloat162*>(ol + (size_t)n * 128 + c4 + 2) = __nv_bfloat162{l2, l3};
}

__global__ __launch_bounds__(256, 8) void k_agg256(const float* __restrict__ in,
                         __nv_bfloat16* __restrict__ oh, __nv_bfloat16* __restrict__ ol) {
    const int warp = threadIdx.x >> 5, lane = threadIdx.x & 31;
    const int n = blockIdx.x * 8 + warp;
    const int c8 = lane * 8;
    float dn = g_dinv[n];
    const float* rowp = in + (size_t)n * 256 + c8;
    float4 sa = *reinterpret_cast<const float4*>(rowp);
    float4 sb = *reinterpret_cast<const float4*>(rowp + 4);
    float4 accA, accB;
    accA.x = dn * dn * sa.x; accA.y = dn * dn * sa.y; accA.z = dn * dn * sa.z; accA.w = dn * dn * sa.w;
    accB.x = dn * dn * sb.x; accB.y = dn * dn * sb.y; accB.z = dn * dn * sb.z; accB.w = dn * dn * sb.w;
    const int beg = g_rowptr[n], end = g_rowptr[n + 1];
    for (int base = beg; base < end; base += 32) {
        int cnt = end - base; if (cnt > 32) cnt = 32;
        int   col = 0; float wt = 0.0f;
        if (lane < cnt) { col = g_col[base + lane]; wt = g_wedge[base + lane]; }
        for (int j = 0; j < cnt; j++) {
            int   idx = __shfl_sync(0xFFFFFFFFu, col, j);
            float ww  = __shfl_sync(0xFFFFFFFFu, wt,  j);
            const float* gp = in + (size_t)idx * 256 + c8;
            float4 va = *reinterpret_cast<const float4*>(gp);
            float4 vb = *reinterpret_cast<const float4*>(gp + 4);
            accA.x += ww * va.x; accA.y += ww * va.y; accA.z += ww * va.z; accA.w += ww * va.w;
            accB.x += ww * vb.x; accB.y += ww * vb.y; accB.z += ww * vb.z; accB.w += ww * vb.w;
        }
    }
    __nv_bfloat162 hv[4], lv[4];
    {
        __nv_bfloat16 h0, l0, h1, l1;
        split_bf16(accA.x, h0, l0); split_bf16(accA.y, h1, l1); hv[0] = {h0, h1}; lv[0] = {l0, l1};
        split_bf16(accA.z, h0, l0); split_bf16(accA.w, h1, l1); hv[1] = {h0, h1}; lv[1] = {l0, l1};
        split_bf16(accB.x, h0, l0); split_bf16(accB.y, h1, l1); hv[2] = {h0, h1}; lv[2] = {l0, l1};
        split_bf16(accB.z, h0, l0); split_bf16(accB.w, h1, l1); hv[3] = {h0, h1}; lv[3] = {l0, l1};
    }
    *reinterpret_cast<uint4*>(oh + (size_t)n * 256 + c8) = *reinterpret_cast<uint4*>(hv);
    *reinterpret_cast<uint4*>(ol + (size_t)n * 256 + c8) = *reinterpret_cast<uint4*>(lv);
}

// ================= split-bf16 mma.sync GEMM (BM, BN tiled) =================
struct MJobs {
    const __nv_bfloat16* Ah[3];
    const __nv_bfloat16* Al[3];
    const __nv_bfloat16* Bh[3];
    const __nv_bfloat16* Bl[3];
    const float*         bias[3];
    float*               C[3];
    __nv_bfloat16*       Cbh[3];
    __nv_bfloat16*       Cbl[3];
    int                  lda[3];
    int                  ldc[3];
    int                  split[3];
};

template <int BM, int NN, int KK>
__global__ __launch_bounds__(256, 3) void k_mma(MJobs jobs, int do_relu) {
    extern __shared__ __align__(16) unsigned char smem[];
    constexpr int NCH = KK / 8;
    constexpr int AB  = BM * KK * 2;
    constexpr int BB  = NN * KK * 2;
    constexpr int NI  = NN / 32;
    constexpr int MI  = BM / 32;
    constexpr int KSTEPS = KK / 16;

    const int job = blockIdx.z;
    const int bm  = blockIdx.y * BM;
    const int bn  = blockIdx.x * NN;      // N-tile offset
    const int tid = threadIdx.x;
    const int lane = tid & 31, warp = tid >> 5;
    const int wm = (warp >> 2) * (BM / 2);
    const int wn = (warp & 3) * (NN / 4);

    const __nv_bfloat16* Ah = jobs.Ah[job];
    const __nv_bfloat16* Al = jobs.Al[job];
    const int lda = jobs.lda[job];

    {
        const int ldach = lda / 8;
        uint4* s = reinterpret_cast<uint4*>(smem);
        for (int idx = tid; idx < BM * NCH; idx += 256) {
            int r = idx / NCH, cc = idx % NCH;
            long gr = bm + r; if (gr >= N_NODES) gr = N_NODES - 1;
            int sp = r * NCH + (cc ^ (r & 7));
            s[sp]           = reinterpret_cast<const uint4*>(Ah)[gr * ldach + cc];
            s[sp + AB / 16] = reinterpret_cast<const uint4*>(Al)[gr * ldach + cc];
        }
        const size_t boffel = (size_t)bn * KK / 8;   // uint4 offset of N-tile
        const uint4* bh = reinterpret_cast<const uint4*>(jobs.Bh[job]) + boffel;
        const uint4* bl = reinterpret_cast<const uint4*>(jobs.Bl[job]) + boffel;
        uint4* sb = reinterpret_cast<uint4*>(smem + 2 * AB);
        for (int idx = tid; idx < NN * NCH; idx += 256) {
            int r = idx / NCH, cc = idx % NCH;
            int sp = r * NCH + (cc ^ (r & 7));
            sb[sp]           = bh[idx];
            sb[sp + BB / 16] = bl[idx];
        }
    }
    __syncthreads();

    const uint32_t sbase = smem_u32(smem);
    const int group = lane >> 3, within = lane & 7;
    const int kaddA = group >> 1;
    uint32_t abyte[MI]; int rx[MI];
    {
        int mrow = wm + (group & 1) * 8 + within;
#pragma unroll
        for (int mi = 0; mi < MI; mi++) {
            int r = mrow + mi * 16;
            abyte[mi] = (uint32_t)(r * NCH) << 4;
            rx[mi] = r & 7;
        }
    }
    const int laneB = lane & 15;
    const int kaddB = laneB >> 3, withinB = laneB & 7;
    uint32_t bbyte[NI]; int nx[NI];
#pragma unroll
    for (int ni = 0; ni < NI; ni++) {
        int r = wn + ni * 8 + withinB;
        bbyte[ni] = (uint32_t)(r * NCH) << 4;
        nx[ni] = r & 7;
    }

    float acc[MI][NI][4];
#pragma unroll
    for (int mi = 0; mi < MI; mi++)
#pragma unroll
        for (int ni = 0; ni < NI; ni++)
#pragma unroll
            for (int q = 0; q < 4; q++) acc[mi][ni][q] = 0.0f;

#pragma unroll 1
    for (int pass = 0; pass < 3; pass++) {
        const uint32_t aoff = sbase + (pass == 2 ? AB : 0);
        const uint32_t boff = sbase + 2 * AB + (pass == 1 ? BB : 0);
#pragma unroll
        for (int s = 0; s < KSTEPS; s++) {
            const int kc = s * 2;
            uint32_t bf[NI][2];
#pragma unroll
            for (int ni = 0; ni < NI; ni++)
                ldsm_x2(bf[ni], boff + bbyte[ni] + ((uint32_t)((kc + kaddB) ^ nx[ni]) << 4));
#pragma unroll
            for (int mi = 0; mi < MI; mi++) {
                uint32_t af[4];
                ldsm_x4(af, aoff + abyte[mi] + ((uint32_t)((kc + kaddA) ^ rx[mi]) << 4));
#pragma unroll
                for (int ni = 0; ni < NI; ni++)
                    mma_bf16(acc[mi][ni], af, bf[ni]);
            }
        }
    }

    const float* bias = jobs.bias[job];
    float* C = jobs.C[job];
    __nv_bfloat16* Cbh = jobs.Cbh[job];
    __nv_bfloat16* Cbl = jobs.Cbl[job];
    const int ldc = jobs.ldc[job];
    const int splt = jobs.split[job];
    const int g = lane >> 2, tc = lane & 3;
#pragma unroll
    for (int mi = 0; mi < MI; mi++) {
#pragma unroll
        for (int ni = 0; ni < NI; ni++) {
            int n0 = bn + wn + ni * 8 + tc * 2;
            float b0 = bias[n0], b1 = bias[n0 + 1];
            int m0 = bm + wm + mi * 16 + g;
            float v0 = acc[mi][ni][0] + b0, v1 = acc[mi][ni][1] + b1;
            float v2 = acc[mi][ni][2] + b0, v3 = acc[mi][ni][3] + b1;
            if (do_relu) {
                v0 = fmaxf(v0, 0.0f); v1 = fmaxf(v1, 0.0f);
                v2 = fmaxf(v2, 0.0f); v3 = fmaxf(v3, 0.0f);
            }
            if (splt) {
                __nv_bfloat16 h0, l0, h1b, l1;
                if (m0 < N_NODES) {
                    split_bf16(v0, h0, l0); split_bf16(v1, h1b, l1);
                    *reinterpret_cast<__nv_bfloat162*>(Cbh + (size_t)m0 * ldc + n0) = __nv_bfloat162{h0, h1b};
                    *reinterpret_cast<__nv_bfloat162*>(Cbl + (size_t)m0 * ldc + n0) = __nv_bfloat162{l0, l1};
                }
                if (m0 + 8 < N_NODES) {
                    split_bf16(v2, h0, l0); split_bf16(v3, h1b, l1);
                    *reinterpret_cast<__nv_bfloat162*>(Cbh + (size_t)(m0 + 8) * ldc + n0) = __nv_bfloat162{h0, h1b};
                    *reinterpret_cast<__nv_bfloat162*>(Cbl + (size_t)(m0 + 8) * ldc + n0) = __nv_bfloat162{l0, l1};
                }
            } else {
                if (m0 < N_NODES)
                    *reinterpret_cast<float2*>(C + (size_t)m0 * ldc + n0) = make_float2(v0, v1);
                if (m0 + 8 < N_NODES)
                    *reinterpret_cast<float2*>(C + (size_t)(m0 + 8) * ldc + n0) = make_float2(v2, v3);
            }
        }
    }
}

// ================= attention fusion (2 nodes/block, writes split bf16 meta) =================
__global__ void k_attn(const float* __restrict__ watt, const float* __restrict__ batt) {
    const int half = threadIdx.x >> 7;
    const int c = threadIdx.x & 127;
    const int n = blockIdx.x * 2 + half;
    float h1v = g_h1[n * 128 + c];
    float h2v = g_h2[n * 128 + c];
    float wa = watt[c];
    float p1 = h1v * wa;
    float p2 = h2v * wa;
#pragma unroll
    for (int o = 16; o > 0; o >>= 1) {
        p1 += __shfl_down_sync(0xFFFFFFFFu, p1, o);
        p2 += __shfl_down_sync(0xFFFFFFFFu, p2, o);
    }
    __shared__ float s1[8], s2[8];
    __shared__ float a1s[2];
    int w = threadIdx.x >> 5;
    if ((threadIdx.x & 31) == 0) { s1[w] = p1; s2[w] = p2; }
    __syncthreads();
    if (c == 0) {
        int b = half * 4;
        float S1 = s1[b] + s1[b+1] + s1[b+2] + s1[b+3] + batt[0];
        float S2 = s2[b] + s2[b+1] + s2[b+2] + s2[b+3] + batt[0];
        a1s[half] = 1.0f / (1.0f + expf(S2 - S1));
    }
    __syncthreads();
    float a1 = a1s[half];
    float v = a1 * h1v + (1.0f - a1) * h2v;
    __nv_bfloat16 h, l;
    split_bf16(v, h, l);
    g_combh[n * 256 + 128 + c] = h;
    g_combl[n * 256 + 128 + c] = l;
}

// ================= launch =================
extern "C" void kernel_launch(void* const* d_in, const int* in_sizes, int n_in,
                              void* d_out, int out_size) {
    const float* x    = (const float*)d_in[0];
    const int*   ei32 = (const int*)d_in[1];
    const float* W_s1 = (const float*)d_in[2];
    const float* b_s1 = (const float*)d_in[3];
    const float* W_s2 = (const float*)d_in[4];
    const float* b_s2 = (const float*)d_in[5];
    const float* W_m1 = (const float*)d_in[6];
    const float* b_m1 = (const float*)d_in[7];
    const float* W_m21 = (const float*)d_in[8];
    const float* b_m21 = (const float*)d_in[9];
    const float* W_m22 = (const float*)d_in[10];
    const float* b_m22 = (const float*)d_in[11];
    const float* W_att = (const float*)d_in[12];
    const float* b_att = (const float*)d_in[13];
    const float* W_fc  = (const float*)d_in[14];
    const float* b_fc  = (const float*)d_in[15];
    float* out = (float*)d_out;

    float* bufA; cudaGetSymbolAddress((void**)&bufA, g_bufA);
    float* h1;   cudaGetSymbolAddress((void**)&h1, g_h1);
    float* h2;   cudaGetSymbolAddress((void**)&h2, g_h2);
    __nv_bfloat16 *aggxh, *aggxl, *agg2h, *agg2l, *combh, *combl, *wth, *wtl;
    cudaGetSymbolAddress((void**)&aggxh, g_aggxh);
    cudaGetSymbolAddress((void**)&aggxl, g_aggxl);
    cudaGetSymbolAddress((void**)&agg2h, g_agg2h);
    cudaGetSymbolAddress((void**)&agg2l, g_agg2l);
    cudaGetSymbolAddress((void**)&combh, g_combh);
    cudaGetSymbolAddress((void**)&combl, g_combl);
    cudaGetSymbolAddress((void**)&wth, g_wth);
    cudaGetSymbolAddress((void**)&wtl, g_wtl);

    // layer GEMMs: BM=64, BN=64 -> smem 64KB -> occupancy 3
    const int SM_L = 2 * (64 * 128 * 2) + 2 * (64 * 128 * 2);     // 65536
    const int SM64 = 2 * (128 * 256 * 2) + 2 * (64 * 256 * 2);    // 196608 (FC, occ 1)
    static bool attr_done = false;
    if (!attr_done) {
        cudaFuncSetAttribute(k_mma<64, 64, 128>,  cudaFuncAttributeMaxDynamicSharedMemorySize, SM_L);
        cudaFuncSetAttribute(k_mma<128, 64, 256>, cudaFuncAttributeMaxDynamicSharedMemorySize, SM64);
        attr_done = true;
    }

    const int TB = 256;
    k_detect_init<<<(N_NODES + TB - 1) / TB, TB>>>(ei32);
    k_extract_count<<<(N_EDGES + TB - 1) / TB, TB>>>(ei32);
    k_scan_dinv<<<1, 1024>>>();
    k_fill<<<(N_EDGES + TB - 1) / TB, TB>>>();

    {
        PrepB p;
        p.W[0] = W_s1;  p.K[0] = 128; p.N[0] = 128;
        p.W[1] = W_m21; p.K[1] = 128; p.N[1] = 128;
        p.W[2] = W_m1;  p.K[2] = 128; p.N[2] = 128;
        p.W[3] = W_s2;  p.K[3] = 128; p.N[3] = 128;
        p.W[4] = W_m22; p.K[4] = 128; p.N[4] = 128;
        p.W[5] = W_fc;  p.K[5] = 256; p.N[5] = 64;
        k_prepB<<<6, 256>>>(p);
    }

    k_agg128<<<N_NODES / 8, 256>>>(x, aggxh, aggxl);

    const int MT64 = (N_NODES + 63) / 64;   // 782

    {
        MJobs j = {};
        for (int q = 0; q < 3; q++) { j.Ah[q] = aggxh; j.Al[q] = aggxl; j.lda[q] = 128; j.split[q] = 0; }
        j.Bh[0] = wth + 0 * 16384; j.Bl[0] = wtl + 0 * 16384; j.bias[0] = b_s1;  j.C[0] = bufA;       j.ldc[0] = 256;
        j.Bh[1] = wth + 1 * 16384; j.Bl[1] = wtl + 1 * 16384; j.bias[1] = b_m21; j.C[1] = bufA + 128; j.ldc[1] = 256;
        j.Bh[2] = wth + 2 * 16384; j.Bl[2] = wtl + 2 * 16384; j.bias[2] = b_m1;  j.C[2] = h1;         j.ldc[2] = 128;
        k_mma<64, 64, 128><<<dim3(2, MT64, 3), 256, SM_L>>>(j, 1);
    }

    k_agg256<<<N_NODES / 8, 256>>>(bufA, agg2h, agg2l);

    {
        MJobs j = {};
        j.Ah[0] = agg2h;       j.Al[0] = agg2l;       j.lda[0] = 256;
        j.Ah[1] = agg2h + 128; j.Al[1] = agg2l + 128; j.lda[1] = 256;
        j.Ah[2] = j.Ah[0];     j.Al[2] = j.Al[0];     j.lda[2] = 256;
        j.Bh[0] = wth + 3 * 16384; j.Bl[0] = wtl + 3 * 16384; j.bias[0] = b_s2;
        j.Cbh[0] = combh; j.Cbl[0] = combl; j.ldc[0] = 256; j.split[0] = 1;
        j.Bh[1] = wth + 4 * 16384; j.Bl[1] = wtl + 4 * 16384; j.bias[1] = b_m22;
        j.C[1] = h2; j.ldc[1] = 128; j.split[1] = 0;
        j.Bh[2] = j.Bh[0]; j.Bl[2] = j.Bl[0]; j.bias[2] = j.bias[0];
        j.Cbh[2] = j.Cbh[0]; j.Cbl[2] = j.Cbl[0]; j.ldc[2] = j.ldc[0]; j.split[2] = 1;
        k_mma<64, 64, 128><<<dim3(2, MT64, 2), 256, SM_L>>>(j, 1);
    }

    k_attn<<<N_NODES / 2, 256>>>(W_att, b_att);

    {
        MJobs j = {};
        for (int q = 0; q < 3; q++) {
            j.Ah[q] = combh; j.Al[q] = combl; j.lda[q] = 256;
            j.Bh[q] = wth + 5 * 16384; j.Bl[q] = wtl + 5 * 16384;
            j.bias[q] = b_fc; j.C[q] = out; j.ldc[q] = 64; j.split[q] = 0;
        }
        k_mma<128, 64, 256><<<dim3(1, (N_NODES + 127) / 128, 1), 256, SM64>>>(j, 0);
    }

    (void)in_sizes; (void)n_in; (void)out_size;
}

// round 10
// speedup vs baseline: 1.1413x; 1.1413x over previous
#include <cuda_runtime.h>
#include <cuda_fp16.h>
#include <math.h>
#include <cstdint>

#define N_NODES 50000
#define N_EDGES 800000

// ================= scratch =================
__device__ int   g_is64;
__device__ int   g_src[N_EDGES];
__device__ int   g_dst[N_EDGES];
__device__ int   g_edeg[N_NODES];
__device__ float g_dinv[N_NODES];
__device__ int   g_rowptr[N_NODES + 1];
__device__ int   g_cursor[N_NODES];
__device__ int   g_col[N_EDGES];
__device__ float g_wedge[N_EDGES];

__device__ float g_bufA[N_NODES * 256];   // [h_s1 | h2a] fp32 (feeds agg256)
__device__ float g_h1[N_NODES * 128];
__device__ float g_h2[N_NODES * 128];

// fp16 operands (A-side unsplit; weights split hi/lo)
__device__ __half g_aggx[N_NODES * 128];
__device__ __half g_agg2[N_NODES * 256];
__device__ __half g_comb[N_NODES * 256];   // [h_struct | h_meta]
__device__ __half g_wth[6][16384];
__device__ __half g_wtl[6][16384];

// ================= helpers =================
__device__ __forceinline__ uint32_t smem_u32(const void* p) {
    uint32_t a;
    asm("{ .reg .u64 t; cvta.to.shared.u64 t, %1; cvt.u32.u64 %0, t; }" : "=r"(a) : "l"(p));
    return a;
}
__device__ __forceinline__ void ldsm_x4(uint32_t* r, uint32_t addr) {
    asm volatile("ldmatrix.sync.aligned.m8n8.x4.shared.b16 {%0,%1,%2,%3}, [%4];"
                 : "=r"(r[0]), "=r"(r[1]), "=r"(r[2]), "=r"(r[3]) : "r"(addr));
}
__device__ __forceinline__ void ldsm_x2(uint32_t* r, uint32_t addr) {
    asm volatile("ldmatrix.sync.aligned.m8n8.x2.shared.b16 {%0,%1}, [%2];"
                 : "=r"(r[0]), "=r"(r[1]) : "r"(addr));
}
__device__ __forceinline__ void mma_f16(float* d, const uint32_t* a, const uint32_t* b) {
    asm volatile("mma.sync.aligned.m16n8k16.row.col.f32.f16.f16.f32 "
                 "{%0,%1,%2,%3}, {%4,%5,%6,%7}, {%8,%9}, {%0,%1,%2,%3};"
                 : "+f"(d[0]), "+f"(d[1]), "+f"(d[2]), "+f"(d[3])
                 : "r"(a[0]), "r"(a[1]), "r"(a[2]), "r"(a[3]), "r"(b[0]), "r"(b[1]));
}
__device__ __forceinline__ void split_f16(float v, __half& h, __half& l) {
    __half hb = __float2half_rn(v);
    h = hb;
    l = __float2half_rn(v - __half2float(hb));
}

// ================= fused detect + edeg zero =================
__global__ void k_detect_init(const int* __restrict__ ei32) {
    int i = blockIdx.x * blockDim.x + threadIdx.x;
    if (i < N_NODES) g_edeg[i] = 0;
    if (blockIdx.x == 0) {
        __shared__ int nz;
        if (threadIdx.x == 0) nz = 0;
        __syncthreads();
        int local = 0;
        for (int q = threadIdx.x; q < 2048; q += blockDim.x)
            if (ei32[2 * q + 1] != 0) local = 1;
        if (local) atomicOr(&nz, 1);
        __syncthreads();
        if (threadIdx.x == 0) g_is64 = nz ? 0 : 1;
    }
}

// ================= fused extract + count =================
__global__ void k_extract_count(const int* __restrict__ ei32) {
    int e = blockIdx.x * blockDim.x + threadIdx.x;
    if (e < N_EDGES) {
        int s, d;
        if (g_is64) { s = ei32[2 * e]; d = ei32[2 * (N_EDGES + e)]; }
        else        { s = ei32[e];     d = ei32[N_EDGES + e]; }
        g_src[e] = s; g_dst[e] = d;
        atomicAdd(&g_edeg[d], 1);
    }
}

// ================= fused scan + dinv =================
__global__ void k_scan_dinv() {
    __shared__ int part[1024];
    const int t = threadIdx.x;
    const int CH = (N_NODES + 1023) / 1024;
    int start = t * CH;
    int s = 0;
    for (int i = 0; i < CH; i++) { int idx = start + i; if (idx < N_NODES) s += g_edeg[idx]; }
    part[t] = s;
    __syncthreads();
    for (int off = 1; off < 1024; off <<= 1) {
        int v = (t >= off) ? part[t - off] : 0;
        __syncthreads();
        part[t] += v;
        __syncthreads();
    }
    int run = (t == 0) ? 0 : part[t - 1];
    for (int i = 0; i < CH; i++) {
        int idx = start + i;
        if (idx < N_NODES) {
            g_rowptr[idx] = run;
            g_cursor[idx] = run;
            g_dinv[idx] = rsqrtf((float)(g_edeg[idx] + 1));
            run += g_edeg[idx];
        }
    }
    if (t == 1023) g_rowptr[N_NODES] = run;
}

__global__ void k_fill() {
    int e = blockIdx.x * blockDim.x + threadIdx.x;
    if (e < N_EDGES) {
        int s = g_src[e], d = g_dst[e];
        int p = atomicAdd(&g_cursor[d], 1);
        g_col[p] = s;
        g_wedge[p] = g_dinv[s] * g_dinv[d];
    }
}

// weights -> transposed split fp16: Wt[n][k] from W[k][n]
struct PrepB { const float* W[6]; int K[6]; int N[6]; };
__global__ void k_prepB(PrepB p) {
    int b = blockIdx.x;
    const float* W = p.W[b];
    int K = p.K[b], N = p.N[b];
    for (int idx = threadIdx.x; idx < K * N; idx += blockDim.x) {
        int k = idx / N, n = idx % N;
        split_f16(W[idx], g_wth[b][n * K + k], g_wtl[b][n * K + k]);
    }
}

// ================= warp-per-node aggregation (emit fp16) =================
__global__ __launch_bounds__(256, 8) void k_agg128(const float* __restrict__ in,
                                                   __half* __restrict__ oh) {
    const int warp = threadIdx.x >> 5, lane = threadIdx.x & 31;
    const int n = blockIdx.x * 8 + warp;
    const int c4 = lane * 4;
    float dn = g_dinv[n];
    float4 self = *reinterpret_cast<const float4*>(in + (size_t)n * 128 + c4);
    float4 acc;
    acc.x = dn * dn * self.x; acc.y = dn * dn * self.y;
    acc.z = dn * dn * self.z; acc.w = dn * dn * self.w;
    const int beg = g_rowptr[n], end = g_rowptr[n + 1];
    for (int base = beg; base < end; base += 32) {
        int cnt = end - base; if (cnt > 32) cnt = 32;
        int   col = 0; float wt = 0.0f;
        if (lane < cnt) { col = g_col[base + lane]; wt = g_wedge[base + lane]; }
        for (int j = 0; j < cnt; j++) {
            int   idx = __shfl_sync(0xFFFFFFFFu, col, j);
            float ww  = __shfl_sync(0xFFFFFFFFu, wt,  j);
            float4 v = *reinterpret_cast<const float4*>(in + (size_t)idx * 128 + c4);
            acc.x += ww * v.x; acc.y += ww * v.y; acc.z += ww * v.z; acc.w += ww * v.w;
        }
    }
    __half2 o0 = {__float2half_rn(acc.x), __float2half_rn(acc.y)};
    __half2 o1 = {__float2half_rn(acc.z), __float2half_rn(acc.w)};
    *reinterpret_cast<__half2*>(oh + (size_t)n * 128 + c4)     = o0;
    *reinterpret_cast<__half2*>(oh + (size_t)n * 128 + c4 + 2) = o1;
}

__global__ __launch_bounds__(256, 8) void k_agg256(const float* __restrict__ in,
                                                   __half* __restrict__ oh) {
    const int warp = threadIdx.x >> 5, lane = threadIdx.x & 31;
    const int n = blockIdx.x * 8 + warp;
    const int c8 = lane * 8;
    float dn = g_dinv[n];
    const float* rowp = in + (size_t)n * 256 + c8;
    float4 sa = *reinterpret_cast<const float4*>(rowp);
    float4 sb = *reinterpret_cast<const float4*>(rowp + 4);
    float4 accA, accB;
    accA.x = dn * dn * sa.x; accA.y = dn * dn * sa.y; accA.z = dn * dn * sa.z; accA.w = dn * dn * sa.w;
    accB.x = dn * dn * sb.x; accB.y = dn * dn * sb.y; accB.z = dn * dn * sb.z; accB.w = dn * dn * sb.w;
    const int beg = g_rowptr[n], end = g_rowptr[n + 1];
    for (int base = beg; base < end; base += 32) {
        int cnt = end - base; if (cnt > 32) cnt = 32;
        int   col = 0; float wt = 0.0f;
        if (lane < cnt) { col = g_col[base + lane]; wt = g_wedge[base + lane]; }
        for (int j = 0; j < cnt; j++) {
            int   idx = __shfl_sync(0xFFFFFFFFu, col, j);
            float ww  = __shfl_sync(0xFFFFFFFFu, wt,  j);
            const float* gp = in + (size_t)idx * 256 + c8;
            float4 va = *reinterpret_cast<const float4*>(gp);
            float4 vb = *reinterpret_cast<const float4*>(gp + 4);
            accA.x += ww * va.x; accA.y += ww * va.y; accA.z += ww * va.z; accA.w += ww * va.w;
            accB.x += ww * vb.x; accB.y += ww * vb.y; accB.z += ww * vb.z; accB.w += ww * vb.w;
        }
    }
    __half2 hv[4];
    hv[0] = {__float2half_rn(accA.x), __float2half_rn(accA.y)};
    hv[1] = {__float2half_rn(accA.z), __float2half_rn(accA.w)};
    hv[2] = {__float2half_rn(accB.x), __float2half_rn(accB.y)};
    hv[3] = {__float2half_rn(accB.z), __float2half_rn(accB.w)};
    *reinterpret_cast<uint4*>(oh + (size_t)n * 256 + c8) = *reinterpret_cast<uint4*>(hv);
}

// ================= fp16 2-pass mma.sync GEMM (A unsplit, W split) =================
struct MJobs {
    const __half* A[3];
    const __half* Bh[3];
    const __half* Bl[3];
    const float*  bias[3];
    float*        C[3];
    __half*       Ch[3];
    int           lda[3];
    int           ldc[3];
    int           split[3];   // 1 => write fp16 to Ch instead of fp32 C
};

template <int BM, int NN, int KK>
__global__ __launch_bounds__(256, 2) void k_mma(MJobs jobs, int do_relu) {
    extern __shared__ __align__(16) unsigned char smem[];
    constexpr int NCH = KK / 8;
    constexpr int AB  = BM * KK * 2;
    constexpr int BB  = NN * KK * 2;
    constexpr int NI  = NN / 32;
    constexpr int MI  = BM / 32;
    constexpr int KSTEPS = KK / 16;

    const int job = blockIdx.z;
    const int bm  = blockIdx.y * BM;
    const int tid = threadIdx.x;
    const int lane = tid & 31, warp = tid >> 5;
    const int wm = (warp >> 2) * (BM / 2);
    const int wn = (warp & 3) * (NN / 4);

    const __half* A = jobs.A[job];
    const int lda = jobs.lda[job];

    {
        const int ldach = lda / 8;
        uint4* s = reinterpret_cast<uint4*>(smem);
        for (int idx = tid; idx < BM * NCH; idx += 256) {
            int r = idx / NCH, cc = idx % NCH;
            long gr = bm + r; if (gr >= N_NODES) gr = N_NODES - 1;
            int sp = r * NCH + (cc ^ (r & 7));
            s[sp] = reinterpret_cast<const uint4*>(A)[gr * ldach + cc];
        }
        const uint4* bh = reinterpret_cast<const uint4*>(jobs.Bh[job]);
        const uint4* bl = reinterpret_cast<const uint4*>(jobs.Bl[job]);
        uint4* sb = reinterpret_cast<uint4*>(smem + AB);
        for (int idx = tid; idx < NN * NCH; idx += 256) {
            int r = idx / NCH, cc = idx % NCH;
            int sp = r * NCH + (cc ^ (r & 7));
            sb[sp]           = bh[idx];
            sb[sp + BB / 16] = bl[idx];
        }
    }
    __syncthreads();

    const uint32_t sbase = smem_u32(smem);
    const int group = lane >> 3, within = lane & 7;
    const int kaddA = group >> 1;
    uint32_t abyte[MI]; int rx[MI];
    {
        int mrow = wm + (group & 1) * 8 + within;
#pragma unroll
        for (int mi = 0; mi < MI; mi++) {
            int r = mrow + mi * 16;
            abyte[mi] = (uint32_t)(r * NCH) << 4;
            rx[mi] = r & 7;
        }
    }
    const int laneB = lane & 15;
    const int kaddB = laneB >> 3, withinB = laneB & 7;
    uint32_t bbyte[NI]; int nx[NI];
#pragma unroll
    for (int ni = 0; ni < NI; ni++) {
        int r = wn + ni * 8 + withinB;
        bbyte[ni] = (uint32_t)(r * NCH) << 4;
        nx[ni] = r & 7;
    }

    float acc[MI][NI][4];
#pragma unroll
    for (int mi = 0; mi < MI; mi++)
#pragma unroll
        for (int ni = 0; ni < NI; ni++)
#pragma unroll
            for (int q = 0; q < 4; q++) acc[mi][ni][q] = 0.0f;

    // 2 passes: A*Wh then A*Wl
#pragma unroll 1
    for (int pass = 0; pass < 2; pass++) {
        const uint32_t aoff = sbase;
        const uint32_t boff = sbase + AB + pass * BB;
#pragma unroll
        for (int s = 0; s < KSTEPS; s++) {
            const int kc = s * 2;
            uint32_t bf[NI][2];
#pragma unroll
            for (int ni = 0; ni < NI; ni++)
                ldsm_x2(bf[ni], boff + bbyte[ni] + ((uint32_t)((kc + kaddB) ^ nx[ni]) << 4));
#pragma unroll
            for (int mi = 0; mi < MI; mi++) {
                uint32_t af[4];
                ldsm_x4(af, aoff + abyte[mi] + ((uint32_t)((kc + kaddA) ^ rx[mi]) << 4));
#pragma unroll
                for (int ni = 0; ni < NI; ni++)
                    mma_f16(acc[mi][ni], af, bf[ni]);
            }
        }
    }

    const float* bias = jobs.bias[job];
    float* C = jobs.C[job];
    __half* Ch = jobs.Ch[job];
    const int ldc = jobs.ldc[job];
    const int splt = jobs.split[job];
    const int g = lane >> 2, tc = lane & 3;
#pragma unroll
    for (int mi = 0; mi < MI; mi++) {
#pragma unroll
        for (int ni = 0; ni < NI; ni++) {
            int n0 = wn + ni * 8 + tc * 2;
            float b0 = bias[n0], b1 = bias[n0 + 1];
            int m0 = bm + wm + mi * 16 + g;
            float v0 = acc[mi][ni][0] + b0, v1 = acc[mi][ni][1] + b1;
            float v2 = acc[mi][ni][2] + b0, v3 = acc[mi][ni][3] + b1;
            if (do_relu) {
                v0 = fmaxf(v0, 0.0f); v1 = fmaxf(v1, 0.0f);
                v2 = fmaxf(v2, 0.0f); v3 = fmaxf(v3, 0.0f);
            }
            if (splt) {
                if (m0 < N_NODES)
                    *reinterpret_cast<__half2*>(Ch + (size_t)m0 * ldc + n0) =
                        __half2{__float2half_rn(v0), __float2half_rn(v1)};
                if (m0 + 8 < N_NODES)
                    *reinterpret_cast<__half2*>(Ch + (size_t)(m0 + 8) * ldc + n0) =
                        __half2{__float2half_rn(v2), __float2half_rn(v3)};
            } else {
                if (m0 < N_NODES)
                    *reinterpret_cast<float2*>(C + (size_t)m0 * ldc + n0) = make_float2(v0, v1);
                if (m0 + 8 < N_NODES)
                    *reinterpret_cast<float2*>(C + (size_t)(m0 + 8) * ldc + n0) = make_float2(v2, v3);
            }
        }
    }
}

// ================= attention fusion (2 nodes/block, writes fp16 meta) =================
__global__ void k_attn(const float* __restrict__ watt, const float* __restrict__ batt) {
    const int half = threadIdx.x >> 7;
    const int c = threadIdx.x & 127;
    const int n = blockIdx.x * 2 + half;
    float h1v = g_h1[n * 128 + c];
    float h2v = g_h2[n * 128 + c];
    float wa = watt[c];
    float p1 = h1v * wa;
    float p2 = h2v * wa;
#pragma unroll
    for (int o = 16; o > 0; o >>= 1) {
        p1 += __shfl_down_sync(0xFFFFFFFFu, p1, o);
        p2 += __shfl_down_sync(0xFFFFFFFFu, p2, o);
    }
    __shared__ float s1[8], s2[8];
    __shared__ float a1s[2];
    int w = threadIdx.x >> 5;
    if ((threadIdx.x & 31) == 0) { s1[w] = p1; s2[w] = p2; }
    __syncthreads();
    if (c == 0) {
        int b = half * 4;
        float S1 = s1[b] + s1[b+1] + s1[b+2] + s1[b+3] + batt[0];
        float S2 = s2[b] + s2[b+1] + s2[b+2] + s2[b+3] + batt[0];
        a1s[half] = 1.0f / (1.0f + expf(S2 - S1));
    }
    __syncthreads();
    float a1 = a1s[half];
    float v = a1 * h1v + (1.0f - a1) * h2v;
    g_comb[n * 256 + 128 + c] = __float2half_rn(v);
}

// ================= launch =================
extern "C" void kernel_launch(void* const* d_in, const int* in_sizes, int n_in,
                              void* d_out, int out_size) {
    const float* x    = (const float*)d_in[0];
    const int*   ei32 = (const int*)d_in[1];
    const float* W_s1 = (const float*)d_in[2];
    const float* b_s1 = (const float*)d_in[3];
    const float* W_s2 = (const float*)d_in[4];
    const float* b_s2 = (const float*)d_in[5];
    const float* W_m1 = (const float*)d_in[6];
    const float* b_m1 = (const float*)d_in[7];
    const float* W_m21 = (const float*)d_in[8];
    const float* b_m21 = (const float*)d_in[9];
    const float* W_m22 = (const float*)d_in[10];
    const float* b_m22 = (const float*)d_in[11];
    const float* W_att = (const float*)d_in[12];
    const float* b_att = (const float*)d_in[13];
    const float* W_fc  = (const float*)d_in[14];
    const float* b_fc  = (const float*)d_in[15];
    float* out = (float*)d_out;

    float* bufA; cudaGetSymbolAddress((void**)&bufA, g_bufA);
    float* h1;   cudaGetSymbolAddress((void**)&h1, g_h1);
    float* h2;   cudaGetSymbolAddress((void**)&h2, g_h2);
    __half *aggx, *agg2, *comb, *wth, *wtl;
    cudaGetSymbolAddress((void**)&aggx, g_aggx);
    cudaGetSymbolAddress((void**)&agg2, g_agg2);
    cudaGetSymbolAddress((void**)&comb, g_comb);
    cudaGetSymbolAddress((void**)&wth, g_wth);
    cudaGetSymbolAddress((void**)&wtl, g_wtl);

    // layer GEMMs: BM=64, BN=128, KK=128: A 16KB + B 2x32KB = 80KB -> occ 2
    const int SM_L  = 64 * 128 * 2 + 2 * (128 * 128 * 2);   // 81920
    // FC: BM=64, NN=64, KK=256: A 32KB + B 2x32KB = 96KB -> occ 2
    const int SM_FC = 64 * 256 * 2 + 2 * (64 * 256 * 2);    // 98304
    static bool attr_done = false;
    if (!attr_done) {
        cudaFuncSetAttribute(k_mma<64, 128, 128>, cudaFuncAttributeMaxDynamicSharedMemorySize, SM_L);
        cudaFuncSetAttribute(k_mma<64, 64, 256>,  cudaFuncAttributeMaxDynamicSharedMemorySize, SM_FC);
        attr_done = true;
    }

    const int TB = 256;
    k_detect_init<<<(N_NODES + TB - 1) / TB, TB>>>(ei32);
    k_extract_count<<<(N_EDGES + TB - 1) / TB, TB>>>(ei32);
    k_scan_dinv<<<1, 1024>>>();
    k_fill<<<(N_EDGES + TB - 1) / TB, TB>>>();

    {
        PrepB p;
        p.W[0] = W_s1;  p.K[0] = 128; p.N[0] = 128;
        p.W[1] = W_m21; p.K[1] = 128; p.N[1] = 128;
        p.W[2] = W_m1;  p.K[2] = 128; p.N[2] = 128;
        p.W[3] = W_s2;  p.K[3] = 128; p.N[3] = 128;
        p.W[4] = W_m22; p.K[4] = 128; p.N[4] = 128;
        p.W[5] = W_fc;  p.K[5] = 256; p.N[5] = 64;
        k_prepB<<<6, 256>>>(p);
    }

    k_agg128<<<N_NODES / 8, 256>>>(x, aggx);

    const int MT64 = (N_NODES + 63) / 64;   // 782

    {
        MJobs j = {};
        for (int q = 0; q < 3; q++) { j.A[q] = aggx; j.lda[q] = 128; j.split[q] = 0; }
        j.Bh[0] = wth + 0 * 16384; j.Bl[0] = wtl + 0 * 16384; j.bias[0] = b_s1;  j.C[0] = bufA;       j.ldc[0] = 256;
        j.Bh[1] = wth + 1 * 16384; j.Bl[1] = wtl + 1 * 16384; j.bias[1] = b_m21; j.C[1] = bufA + 128; j.ldc[1] = 256;
        j.Bh[2] = wth + 2 * 16384; j.Bl[2] = wtl + 2 * 16384; j.bias[2] = b_m1;  j.C[2] = h1;         j.ldc[2] = 128;
        k_mma<64, 128, 128><<<dim3(1, MT64, 3), 256, SM_L>>>(j, 1);
    }

    k_agg256<<<N_NODES / 8, 256>>>(bufA, agg2);

    {
        MJobs j = {};
        j.A[0] = agg2;       j.lda[0] = 256;
        j.A[1] = agg2 + 128; j.lda[1] = 256;
        j.A[2] = j.A[0];     j.lda[2] = 256;
        // job0: h_struct -> comb[:, :128] as fp16
        j.Bh[0] = wth + 3 * 16384; j.Bl[0] = wtl + 3 * 16384; j.bias[0] = b_s2;
        j.Ch[0] = comb; j.ldc[0] = 256; j.split[0] = 1;
        // job1: h2 fp32
        j.Bh[1] = wth + 4 * 16384; j.Bl[1] = wtl + 4 * 16384; j.bias[1] = b_m22;
        j.C[1] = h2; j.ldc[1] = 128; j.split[1] = 0;
        j.Bh[2] = j.Bh[0]; j.Bl[2] = j.Bl[0]; j.bias[2] = j.bias[0];
        j.Ch[2] = j.Ch[0]; j.ldc[2] = j.ldc[0]; j.split[2] = 1;
        k_mma<64, 128, 128><<<dim3(1, MT64, 2), 256, SM_L>>>(j, 1);
    }

    k_attn<<<N_NODES / 2, 256>>>(W_att, b_att);

    {
        MJobs j = {};
        for (int q = 0; q < 3; q++) {
            j.A[q] = comb; j.lda[q] = 256;
            j.Bh[q] = wth + 5 * 16384; j.Bl[q] = wtl + 5 * 16384;
            j.bias[q] = b_fc; j.C[q] = out; j.ldc[q] = 64; j.split[q] = 0;
        }
        k_mma<64, 64, 256><<<dim3(1, MT64, 1), 256, SM_FC>>>(j, 0);
    }

    (void)in_sizes; (void)n_in; (void)out_size;
}

// round 11
// speedup vs baseline: 1.2347x; 1.0818x over previous
#include <cuda_runtime.h>
#include <cuda_fp16.h>
#include <math.h>
#include <cstdint>

#define N_NODES 50000
#define N_EDGES 800000

// ================= scratch =================
__device__ int   g_is64;
__device__ int   g_edeg[N_NODES];
__device__ float g_dinv[N_NODES];
__device__ int   g_rowptr[N_NODES + 1];
__device__ int   g_cursor[N_NODES];
__device__ int   g_col[N_EDGES];
__device__ float g_wedge[N_EDGES];

__device__ float g_h1[N_NODES * 128];
__device__ float g_h2[N_NODES * 128];

// fp16 buffers
__device__ __half g_xh[N_NODES * 128];      // x in fp16 (gather source)
__device__ __half g_bufA[N_NODES * 256];    // [h_s1 | h2a] fp16 (gather source)
__device__ __half g_aggx[N_NODES * 128];    // agg(x) fp16 (GEMM A)
__device__ __half g_agg2[N_NODES * 256];    // agg(bufA) fp16 (GEMM A)
__device__ __half g_comb[N_NODES * 256];    // [h_struct | h_meta] fp16 (GEMM A)
__device__ __half g_wth[6][16384];
__device__ __half g_wtl[6][16384];

// ================= helpers =================
__device__ __forceinline__ uint32_t smem_u32(const void* p) {
    uint32_t a;
    asm("{ .reg .u64 t; cvta.to.shared.u64 t, %1; cvt.u32.u64 %0, t; }" : "=r"(a) : "l"(p));
    return a;
}
__device__ __forceinline__ void ldsm_x4(uint32_t* r, uint32_t addr) {
    asm volatile("ldmatrix.sync.aligned.m8n8.x4.shared.b16 {%0,%1,%2,%3}, [%4];"
                 : "=r"(r[0]), "=r"(r[1]), "=r"(r[2]), "=r"(r[3]) : "r"(addr));
}
__device__ __forceinline__ void ldsm_x2(uint32_t* r, uint32_t addr) {
    asm volatile("ldmatrix.sync.aligned.m8n8.x2.shared.b16 {%0,%1}, [%2];"
                 : "=r"(r[0]), "=r"(r[1]) : "r"(addr));
}
__device__ __forceinline__ void mma_f16(float* d, const uint32_t* a, const uint32_t* b) {
    asm volatile("mma.sync.aligned.m16n8k16.row.col.f32.f16.f16.f32 "
                 "{%0,%1,%2,%3}, {%4,%5,%6,%7}, {%8,%9}, {%0,%1,%2,%3};"
                 : "+f"(d[0]), "+f"(d[1]), "+f"(d[2]), "+f"(d[3])
                 : "r"(a[0]), "r"(a[1]), "r"(a[2]), "r"(a[3]), "r"(b[0]), "r"(b[1]));
}
__device__ __forceinline__ void split_f16(float v, __half& h, __half& l) {
    __half hb = __float2half_rn(v);
    h = hb;
    l = __float2half_rn(v - __half2float(hb));
}

// ================= fused detect + edeg zero =================
__global__ void k_detect_init(const int* __restrict__ ei32) {
    int i = blockIdx.x * blockDim.x + threadIdx.x;
    if (i < N_NODES) g_edeg[i] = 0;
    if (blockIdx.x == 0) {
        __shared__ int nz;
        if (threadIdx.x == 0) nz = 0;
        __syncthreads();
        int local = 0;
        for (int q = threadIdx.x; q < 2048; q += blockDim.x)
            if (ei32[2 * q + 1] != 0) local = 1;
        if (local) atomicOr(&nz, 1);
        __syncthreads();
        if (threadIdx.x == 0) g_is64 = nz ? 0 : 1;
    }
}

// ================= count (reads edge_index directly) =================
__global__ void k_count(const int* __restrict__ ei32) {
    int e = blockIdx.x * blockDim.x + threadIdx.x;
    if (e < N_EDGES) {
        int d = g_is64 ? ei32[2 * (N_EDGES + e)] : ei32[N_EDGES + e];
        atomicAdd(&g_edeg[d], 1);
    }
}

// ================= fused scan + dinv =================
__global__ void k_scan_dinv() {
    __shared__ int part[1024];
    const int t = threadIdx.x;
    const int CH = (N_NODES + 1023) / 1024;
    int start = t * CH;
    int s = 0;
    for (int i = 0; i < CH; i++) { int idx = start + i; if (idx < N_NODES) s += g_edeg[idx]; }
    part[t] = s;
    __syncthreads();
    for (int off = 1; off < 1024; off <<= 1) {
        int v = (t >= off) ? part[t - off] : 0;
        __syncthreads();
        part[t] += v;
        __syncthreads();
    }
    int run = (t == 0) ? 0 : part[t - 1];
    for (int i = 0; i < CH; i++) {
        int idx = start + i;
        if (idx < N_NODES) {
            g_rowptr[idx] = run;
            g_cursor[idx] = run;
            g_dinv[idx] = rsqrtf((float)(g_edeg[idx] + 1));
            run += g_edeg[idx];
        }
    }
    if (t == 1023) g_rowptr[N_NODES] = run;
}

__global__ void k_fill(const int* __restrict__ ei32) {
    int e = blockIdx.x * blockDim.x + threadIdx.x;
    if (e < N_EDGES) {
        int s, d;
        if (g_is64) { s = ei32[2 * e]; d = ei32[2 * (N_EDGES + e)]; }
        else        { s = ei32[e];     d = ei32[N_EDGES + e]; }
        int p = atomicAdd(&g_cursor[d], 1);
        g_col[p] = s;
        g_wedge[p] = g_dinv[s] * g_dinv[d];
    }
}

// x -> fp16 (8 elems/thread)
__global__ void k_convx(const float* __restrict__ x, __half* __restrict__ xh) {
    int i = blockIdx.x * blockDim.x + threadIdx.x;   // 800000 total
    const float4* xp = reinterpret_cast<const float4*>(x) + 2 * (size_t)i;
    float4 a = xp[0], b = xp[1];
    __half2 h[4];
    h[0] = {__float2half_rn(a.x), __float2half_rn(a.y)};
    h[1] = {__float2half_rn(a.z), __float2half_rn(a.w)};
    h[2] = {__float2half_rn(b.x), __float2half_rn(b.y)};
    h[3] = {__float2half_rn(b.z), __float2half_rn(b.w)};
    reinterpret_cast<uint4*>(xh)[i] = *reinterpret_cast<uint4*>(h);
}

// weights -> transposed split fp16
struct PrepB { const float* W[6]; int K[6]; int N[6]; };
__global__ void k_prepB(PrepB p) {
    int b = blockIdx.x;
    const float* W = p.W[b];
    int K = p.K[b], N = p.N[b];
    for (int idx = threadIdx.x; idx < K * N; idx += blockDim.x) {
        int k = idx / N, n = idx % N;
        split_f16(W[idx], g_wth[b][n * K + k], g_wtl[b][n * K + k]);
    }
}

// ================= warp-per-node aggregation (fp16 gather, fp32 accum, fp16 out) =================
__global__ __launch_bounds__(256, 8) void k_agg128(const __half* __restrict__ in,
                                                   __half* __restrict__ oh) {
    const int warp = threadIdx.x >> 5, lane = threadIdx.x & 31;
    const int n = blockIdx.x * 8 + warp;
    const int c4 = lane * 4;
    float dn = g_dinv[n];
    float acc0, acc1, acc2, acc3;
    {
        uint2 sv = *reinterpret_cast<const uint2*>(in + (size_t)n * 128 + c4);
        __half2 s0 = *reinterpret_cast<__half2*>(&sv.x);
        __half2 s1 = *reinterpret_cast<__half2*>(&sv.y);
        float w = dn * dn;
        acc0 = w * __half2float(s0.x); acc1 = w * __half2float(s0.y);
        acc2 = w * __half2float(s1.x); acc3 = w * __half2float(s1.y);
    }
    const int beg = g_rowptr[n], end = g_rowptr[n + 1];
    for (int base = beg; base < end; base += 32) {
        int cnt = end - base; if (cnt > 32) cnt = 32;
        int   col = 0; float wt = 0.0f;
        if (lane < cnt) { col = g_col[base + lane]; wt = g_wedge[base + lane]; }
        for (int j = 0; j < cnt; j++) {
            int   idx = __shfl_sync(0xFFFFFFFFu, col, j);
            float ww  = __shfl_sync(0xFFFFFFFFu, wt,  j);
            uint2 gv = *reinterpret_cast<const uint2*>(in + (size_t)idx * 128 + c4);
            __half2 g0 = *reinterpret_cast<__half2*>(&gv.x);
            __half2 g1 = *reinterpret_cast<__half2*>(&gv.y);
            acc0 += ww * __half2float(g0.x); acc1 += ww * __half2float(g0.y);
            acc2 += ww * __half2float(g1.x); acc3 += ww * __half2float(g1.y);
        }
    }
    __half2 o0 = {__float2half_rn(acc0), __float2half_rn(acc1)};
    __half2 o1 = {__float2half_rn(acc2), __float2half_rn(acc3)};
    *reinterpret_cast<uint2*>(oh + (size_t)n * 128 + c4) = make_uint2(
        *reinterpret_cast<uint32_t*>(&o0), *reinterpret_cast<uint32_t*>(&o1));
}

__global__ __launch_bounds__(256, 8) void k_agg256(const __half* __restrict__ in,
                                                   __half* __restrict__ oh) {
    const int warp = threadIdx.x >> 5, lane = threadIdx.x & 31;
    const int n = blockIdx.x * 8 + warp;
    const int c8 = lane * 8;
    float dn = g_dinv[n];
    float acc[8];
    {
        uint4 sv = *reinterpret_cast<const uint4*>(in + (size_t)n * 256 + c8);
        const __half2* sh = reinterpret_cast<const __half2*>(&sv);
        float w = dn * dn;
#pragma unroll
        for (int q = 0; q < 4; q++) {
            acc[2 * q]     = w * __half2float(sh[q].x);
            acc[2 * q + 1] = w * __half2float(sh[q].y);
        }
    }
    const int beg = g_rowptr[n], end = g_rowptr[n + 1];
    for (int base = beg; base < end; base += 32) {
        int cnt = end - base; if (cnt > 32) cnt = 32;
        int   col = 0; float wt = 0.0f;
        if (lane < cnt) { col = g_col[base + lane]; wt = g_wedge[base + lane]; }
        for (int j = 0; j < cnt; j++) {
            int   idx = __shfl_sync(0xFFFFFFFFu, col, j);
            float ww  = __shfl_sync(0xFFFFFFFFu, wt,  j);
            uint4 gv = *reinterpret_cast<const uint4*>(in + (size_t)idx * 256 + c8);
            const __half2* gh = reinterpret_cast<const __half2*>(&gv);
#pragma unroll
            for (int q = 0; q < 4; q++) {
                acc[2 * q]     += ww * __half2float(gh[q].x);
                acc[2 * q + 1] += ww * __half2float(gh[q].y);
            }
        }
    }
    __half2 hv[4];
#pragma unroll
    for (int q = 0; q < 4; q++)
        hv[q] = {__float2half_rn(acc[2 * q]), __float2half_rn(acc[2 * q + 1])};
    *reinterpret_cast<uint4*>(oh + (size_t)n * 256 + c8) = *reinterpret_cast<uint4*>(hv);
}

// ================= fp16 2-pass mma.sync GEMM (A unsplit, W split) =================
struct MJobs {
    const __half* A[3];
    const __half* Bh[3];
    const __half* Bl[3];
    const float*  bias[3];
    float*        C[3];
    __half*       Ch[3];
    int           lda[3];
    int           ldc[3];
    int           split[3];   // 1 => write fp16 to Ch
};

template <int BM, int NN, int KK>
__global__ __launch_bounds__(256, 2) void k_mma(MJobs jobs, int do_relu) {
    extern __shared__ __align__(16) unsigned char smem[];
    constexpr int NCH = KK / 8;
    constexpr int AB  = BM * KK * 2;
    constexpr int BB  = NN * KK * 2;
    constexpr int NI  = NN / 32;
    constexpr int MI  = BM / 32;
    constexpr int KSTEPS = KK / 16;

    const int job = blockIdx.z;
    const int bm  = blockIdx.y * BM;
    const int tid = threadIdx.x;
    const int lane = tid & 31, warp = tid >> 5;
    const int wm = (warp >> 2) * (BM / 2);
    const int wn = (warp & 3) * (NN / 4);

    const __half* A = jobs.A[job];
    const int lda = jobs.lda[job];

    {
        const int ldach = lda / 8;
        uint4* s = reinterpret_cast<uint4*>(smem);
        for (int idx = tid; idx < BM * NCH; idx += 256) {
            int r = idx / NCH, cc = idx % NCH;
            long gr = bm + r; if (gr >= N_NODES) gr = N_NODES - 1;
            int sp = r * NCH + (cc ^ (r & 7));
            s[sp] = reinterpret_cast<const uint4*>(A)[gr * ldach + cc];
        }
        const uint4* bh = reinterpret_cast<const uint4*>(jobs.Bh[job]);
        const uint4* bl = reinterpret_cast<const uint4*>(jobs.Bl[job]);
        uint4* sb = reinterpret_cast<uint4*>(smem + AB);
        for (int idx = tid; idx < NN * NCH; idx += 256) {
            int r = idx / NCH, cc = idx % NCH;
            int sp = r * NCH + (cc ^ (r & 7));
            sb[sp]           = bh[idx];
            sb[sp + BB / 16] = bl[idx];
        }
    }
    __syncthreads();

    const uint32_t sbase = smem_u32(smem);
    const int group = lane >> 3, within = lane & 7;
    const int kaddA = group >> 1;
    uint32_t abyte[MI]; int rx[MI];
    {
        int mrow = wm + (group & 1) * 8 + within;
#pragma unroll
        for (int mi = 0; mi < MI; mi++) {
            int r = mrow + mi * 16;
            abyte[mi] = (uint32_t)(r * NCH) << 4;
            rx[mi] = r & 7;
        }
    }
    const int laneB = lane & 15;
    const int kaddB = laneB >> 3, withinB = laneB & 7;
    uint32_t bbyte[NI]; int nx[NI];
#pragma unroll
    for (int ni = 0; ni < NI; ni++) {
        int r = wn + ni * 8 + withinB;
        bbyte[ni] = (uint32_t)(r * NCH) << 4;
        nx[ni] = r & 7;
    }

    float acc[MI][NI][4];
#pragma unroll
    for (int mi = 0; mi < MI; mi++)
#pragma unroll
        for (int ni = 0; ni < NI; ni++)
#pragma unroll
            for (int q = 0; q < 4; q++) acc[mi][ni][q] = 0.0f;

#pragma unroll 1
    for (int pass = 0; pass < 2; pass++) {
        const uint32_t aoff = sbase;
        const uint32_t boff = sbase + AB + pass * BB;
#pragma unroll
        for (int s = 0; s < KSTEPS; s++) {
            const int kc = s * 2;
            uint32_t bf[NI][2];
#pragma unroll
            for (int ni = 0; ni < NI; ni++)
                ldsm_x2(bf[ni], boff + bbyte[ni] + ((uint32_t)((kc + kaddB) ^ nx[ni]) << 4));
#pragma unroll
            for (int mi = 0; mi < MI; mi++) {
                uint32_t af[4];
                ldsm_x4(af, aoff + abyte[mi] + ((uint32_t)((kc + kaddA) ^ rx[mi]) << 4));
#pragma unroll
                for (int ni = 0; ni < NI; ni++)
                    mma_f16(acc[mi][ni], af, bf[ni]);
            }
        }
    }

    const float* bias = jobs.bias[job];
    float* C = jobs.C[job];
    __half* Ch = jobs.Ch[job];
    const int ldc = jobs.ldc[job];
    const int splt = jobs.split[job];
    const int g = lane >> 2, tc = lane & 3;
#pragma unroll
    for (int mi = 0; mi < MI; mi++) {
#pragma unroll
        for (int ni = 0; ni < NI; ni++) {
            int n0 = wn + ni * 8 + tc * 2;
            float b0 = bias[n0], b1 = bias[n0 + 1];
            int m0 = bm + wm + mi * 16 + g;
            float v0 = acc[mi][ni][0] + b0, v1 = acc[mi][ni][1] + b1;
            float v2 = acc[mi][ni][2] + b0, v3 = acc[mi][ni][3] + b1;
            if (do_relu) {
                v0 = fmaxf(v0, 0.0f); v1 = fmaxf(v1, 0.0f);
                v2 = fmaxf(v2, 0.0f); v3 = fmaxf(v3, 0.0f);
            }
            if (splt) {
                if (m0 < N_NODES)
                    *reinterpret_cast<__half2*>(Ch + (size_t)m0 * ldc + n0) =
                        __half2{__float2half_rn(v0), __float2half_rn(v1)};
                if (m0 + 8 < N_NODES)
                    *reinterpret_cast<__half2*>(Ch + (size_t)(m0 + 8) * ldc + n0) =
                        __half2{__float2half_rn(v2), __float2half_rn(v3)};
            } else {
                if (m0 < N_NODES)
                    *reinterpret_cast<float2*>(C + (size_t)m0 * ldc + n0) = make_float2(v0, v1);
                if (m0 + 8 < N_NODES)
                    *reinterpret_cast<float2*>(C + (size_t)(m0 + 8) * ldc + n0) = make_float2(v2, v3);
            }
        }
    }
}

// ================= attention fusion (2 nodes/block, writes fp16 meta) =================
__global__ void k_attn(const float* __restrict__ watt, const float* __restrict__ batt) {
    const int half = threadIdx.x >> 7;
    const int c = threadIdx.x & 127;
    const int n = blockIdx.x * 2 + half;
    float h1v = g_h1[n * 128 + c];
    float h2v = g_h2[n * 128 + c];
    float wa = watt[c];
    float p1 = h1v * wa;
    float p2 = h2v * wa;
#pragma unroll
    for (int o = 16; o > 0; o >>= 1) {
        p1 += __shfl_down_sync(0xFFFFFFFFu, p1, o);
        p2 += __shfl_down_sync(0xFFFFFFFFu, p2, o);
    }
    __shared__ float s1[8], s2[8];
    __shared__ float a1s[2];
    int w = threadIdx.x >> 5;
    if ((threadIdx.x & 31) == 0) { s1[w] = p1; s2[w] = p2; }
    __syncthreads();
    if (c == 0) {
        int b = half * 4;
        float S1 = s1[b] + s1[b+1] + s1[b+2] + s1[b+3] + batt[0];
        float S2 = s2[b] + s2[b+1] + s2[b+2] + s2[b+3] + batt[0];
        a1s[half] = 1.0f / (1.0f + expf(S2 - S1));
    }
    __syncthreads();
    float a1 = a1s[half];
    float v = a1 * h1v + (1.0f - a1) * h2v;
    g_comb[n * 256 + 128 + c] = __float2half_rn(v);
}

// ================= launch =================
extern "C" void kernel_launch(void* const* d_in, const int* in_sizes, int n_in,
                              void* d_out, int out_size) {
    const float* x    = (const float*)d_in[0];
    const int*   ei32 = (const int*)d_in[1];
    const float* W_s1 = (const float*)d_in[2];
    const float* b_s1 = (const float*)d_in[3];
    const float* W_s2 = (const float*)d_in[4];
    const float* b_s2 = (const float*)d_in[5];
    const float* W_m1 = (const float*)d_in[6];
    const float* b_m1 = (const float*)d_in[7];
    const float* W_m21 = (const float*)d_in[8];
    const float* b_m21 = (const float*)d_in[9];
    const float* W_m22 = (const float*)d_in[10];
    const float* b_m22 = (const float*)d_in[11];
    const float* W_att = (const float*)d_in[12];
    const float* b_att = (const float*)d_in[13];
    const float* W_fc  = (const float*)d_in[14];
    const float* b_fc  = (const float*)d_in[15];
    float* out = (float*)d_out;

    float* h1;   cudaGetSymbolAddress((void**)&h1, g_h1);
    float* h2;   cudaGetSymbolAddress((void**)&h2, g_h2);
    __half *xh, *bufA, *aggx, *agg2, *comb, *wth, *wtl;
    cudaGetSymbolAddress((void**)&xh, g_xh);
    cudaGetSymbolAddress((void**)&bufA, g_bufA);
    cudaGetSymbolAddress((void**)&aggx, g_aggx);
    cudaGetSymbolAddress((void**)&agg2, g_agg2);
    cudaGetSymbolAddress((void**)&comb, g_comb);
    cudaGetSymbolAddress((void**)&wth, g_wth);
    cudaGetSymbolAddress((void**)&wtl, g_wtl);

    const int SM_L  = 64 * 128 * 2 + 2 * (128 * 128 * 2);   // 81920, occ 2
    const int SM_FC = 64 * 256 * 2 + 2 * (64 * 256 * 2);    // 98304, occ 2
    static bool attr_done = false;
    if (!attr_done) {
        cudaFuncSetAttribute(k_mma<64, 128, 128>, cudaFuncAttributeMaxDynamicSharedMemorySize, SM_L);
        cudaFuncSetAttribute(k_mma<64, 64, 256>,  cudaFuncAttributeMaxDynamicSharedMemorySize, SM_FC);
        attr_done = true;
    }

    const int TB = 256;
    k_detect_init<<<(N_NODES + TB - 1) / TB, TB>>>(ei32);
    k_count<<<(N_EDGES + TB - 1) / TB, TB>>>(ei32);
    k_scan_dinv<<<1, 1024>>>();
    k_fill<<<(N_EDGES + TB - 1) / TB, TB>>>(ei32);
    k_convx<<<(N_NODES * 128 / 8 + TB - 1) / TB, TB>>>(x, xh);

    {
        PrepB p;
        p.W[0] = W_s1;  p.K[0] = 128; p.N[0] = 128;
        p.W[1] = W_m21; p.K[1] = 128; p.N[1] = 128;
        p.W[2] = W_m1;  p.K[2] = 128; p.N[2] = 128;
        p.W[3] = W_s2;  p.K[3] = 128; p.N[3] = 128;
        p.W[4] = W_m22; p.K[4] = 128; p.N[4] = 128;
        p.W[5] = W_fc;  p.K[5] = 256; p.N[5] = 64;
        k_prepB<<<6, 256>>>(p);
    }

    k_agg128<<<N_NODES / 8, 256>>>(xh, aggx);

    const int MT64 = (N_NODES + 63) / 64;   // 782

    {
        MJobs j = {};
        for (int q = 0; q < 3; q++) { j.A[q] = aggx; j.lda[q] = 128; }
        // job0/1 -> bufA fp16 (halves), job2 -> h1 fp32
        j.Bh[0] = wth + 0 * 16384; j.Bl[0] = wtl + 0 * 16384; j.bias[0] = b_s1;
        j.Ch[0] = bufA;       j.ldc[0] = 256; j.split[0] = 1;
        j.Bh[1] = wth + 1 * 16384; j.Bl[1] = wtl + 1 * 16384; j.bias[1] = b_m21;
        j.Ch[1] = bufA + 128; j.ldc[1] = 256; j.split[1] = 1;
        j.Bh[2] = wth + 2 * 16384; j.Bl[2] = wtl + 2 * 16384; j.bias[2] = b_m1;
        j.C[2] = h1; j.ldc[2] = 128; j.split[2] = 0;
        k_mma<64, 128, 128><<<dim3(1, MT64, 3), 256, SM_L>>>(j, 1);
    }

    k_agg256<<<N_NODES / 8, 256>>>(bufA, agg2);

    {
        MJobs j = {};
        j.A[0] = agg2;       j.lda[0] = 256;
        j.A[1] = agg2 + 128; j.lda[1] = 256;
        j.A[2] = j.A[0];     j.lda[2] = 256;
        j.Bh[0] = wth + 3 * 16384; j.Bl[0] = wtl + 3 * 16384; j.bias[0] = b_s2;
        j.Ch[0] = comb; j.ldc[0] = 256; j.split[0] = 1;
        j.Bh[1] = wth + 4 * 16384; j.Bl[1] = wtl + 4 * 16384; j.bias[1] = b_m22;
        j.C[1] = h2; j.ldc[1] = 128; j.split[1] = 0;
        j.Bh[2] = j.Bh[0]; j.Bl[2] = j.Bl[0]; j.bias[2] = j.bias[0];
        j.Ch[2] = j.Ch[0]; j.ldc[2] = j.ldc[0]; j.split[2] = 1;
        k_mma<64, 128, 128><<<dim3(1, MT64, 2), 256, SM_L>>>(j, 1);
    }

    k_attn<<<N_NODES / 2, 256>>>(W_att, b_att);

    {
        MJobs j = {};
        for (int q = 0; q < 3; q++) {
            j.A[q] = comb; j.lda[q] = 256;
            j.Bh[q] = wth + 5 * 16384; j.Bl[q] = wtl + 5 * 16384;
            j.bias[q] = b_fc; j.C[q] = out; j.ldc[q] = 64; j.split[q] = 0;
        }
        k_mma<64, 64, 256><<<dim3(1, MT64, 1), 256, SM_FC>>>(j, 0);
    }

    (void)in_sizes; (void)n_in; (void)out_size;
}

// round 12
// speedup vs baseline: 1.2981x; 1.0514x over previous
#include <cuda_runtime.h>
#include <cuda_fp16.h>
#include <math.h>
#include <cstdint>

#define N_NODES 50000
#define N_EDGES 800000

// ================= scratch =================
__device__ int   g_is64;
__device__ int   g_edeg[N_NODES];
__device__ float g_dinv[N_NODES];
__device__ int   g_rowptr[N_NODES + 1];
__device__ int   g_cursor[N_NODES];
__device__ int   g_col[N_EDGES];
__device__ float g_wedge[N_EDGES];

__device__ float g_h1[N_NODES * 128];
__device__ float g_h2[N_NODES * 128];

// fp16 buffers
__device__ __half g_xh[N_NODES * 128];
__device__ __half g_bufA[N_NODES * 256];
__device__ __half g_aggx[N_NODES * 128];
__device__ __half g_agg2[N_NODES * 256];
__device__ __half g_comb[N_NODES * 256];
__device__ __half g_wth[6][16384];
__device__ __half g_wtl[6][16384];

// ================= helpers =================
__device__ __forceinline__ uint32_t smem_u32(const void* p) {
    uint32_t a;
    asm("{ .reg .u64 t; cvta.to.shared.u64 t, %1; cvt.u32.u64 %0, t; }" : "=r"(a) : "l"(p));
    return a;
}
__device__ __forceinline__ void ldsm_x4(uint32_t* r, uint32_t addr) {
    asm volatile("ldmatrix.sync.aligned.m8n8.x4.shared.b16 {%0,%1,%2,%3}, [%4];"
                 : "=r"(r[0]), "=r"(r[1]), "=r"(r[2]), "=r"(r[3]) : "r"(addr));
}
__device__ __forceinline__ void ldsm_x2(uint32_t* r, uint32_t addr) {
    asm volatile("ldmatrix.sync.aligned.m8n8.x2.shared.b16 {%0,%1}, [%2];"
                 : "=r"(r[0]), "=r"(r[1]) : "r"(addr));
}
__device__ __forceinline__ void mma_f16(float* d, const uint32_t* a, const uint32_t* b) {
    asm volatile("mma.sync.aligned.m16n8k16.row.col.f32.f16.f16.f32 "
                 "{%0,%1,%2,%3}, {%4,%5,%6,%7}, {%8,%9}, {%0,%1,%2,%3};"
                 : "+f"(d[0]), "+f"(d[1]), "+f"(d[2]), "+f"(d[3])
                 : "r"(a[0]), "r"(a[1]), "r"(a[2]), "r"(a[3]), "r"(b[0]), "r"(b[1]));
}
__device__ __forceinline__ void split_f16(float v, __half& h, __half& l) {
    __half hb = __float2half_rn(v);
    h = hb;
    l = __float2half_rn(v - __half2float(hb));
}

// ================= fused detect + edeg zero =================
__global__ void k_detect_init(const int* __restrict__ ei32) {
    int i = blockIdx.x * blockDim.x + threadIdx.x;
    if (i < N_NODES) g_edeg[i] = 0;
    if (blockIdx.x == 0) {
        __shared__ int nz;
        if (threadIdx.x == 0) nz = 0;
        __syncthreads();
        int local = 0;
        for (int q = threadIdx.x; q < 2048; q += blockDim.x)
            if (ei32[2 * q + 1] != 0) local = 1;
        if (local) atomicOr(&nz, 1);
        __syncthreads();
        if (threadIdx.x == 0) g_is64 = nz ? 0 : 1;
    }
}

__global__ void k_count(const int* __restrict__ ei32) {
    int e = blockIdx.x * blockDim.x + threadIdx.x;
    if (e < N_EDGES) {
        int d = g_is64 ? ei32[2 * (N_EDGES + e)] : ei32[N_EDGES + e];
        atomicAdd(&g_edeg[d], 1);
    }
}

__global__ void k_scan_dinv() {
    __shared__ int part[1024];
    const int t = threadIdx.x;
    const int CH = (N_NODES + 1023) / 1024;
    int start = t * CH;
    int s = 0;
    for (int i = 0; i < CH; i++) { int idx = start + i; if (idx < N_NODES) s += g_edeg[idx]; }
    part[t] = s;
    __syncthreads();
    for (int off = 1; off < 1024; off <<= 1) {
        int v = (t >= off) ? part[t - off] : 0;
        __syncthreads();
        part[t] += v;
        __syncthreads();
    }
    int run = (t == 0) ? 0 : part[t - 1];
    for (int i = 0; i < CH; i++) {
        int idx = start + i;
        if (idx < N_NODES) {
            g_rowptr[idx] = run;
            g_cursor[idx] = run;
            g_dinv[idx] = rsqrtf((float)(g_edeg[idx] + 1));
            run += g_edeg[idx];
        }
    }
    if (t == 1023) g_rowptr[N_NODES] = run;
}

__global__ void k_fill(const int* __restrict__ ei32) {
    int e = blockIdx.x * blockDim.x + threadIdx.x;
    if (e < N_EDGES) {
        int s, d;
        if (g_is64) { s = ei32[2 * e]; d = ei32[2 * (N_EDGES + e)]; }
        else        { s = ei32[e];     d = ei32[N_EDGES + e]; }
        int p = atomicAdd(&g_cursor[d], 1);
        g_col[p] = s;
        g_wedge[p] = g_dinv[s] * g_dinv[d];
    }
}

__global__ void k_convx(const float* __restrict__ x, __half* __restrict__ xh) {
    int i = blockIdx.x * blockDim.x + threadIdx.x;
    const float4* xp = reinterpret_cast<const float4*>(x) + 2 * (size_t)i;
    float4 a = xp[0], b = xp[1];
    __half2 h[4];
    h[0] = {__float2half_rn(a.x), __float2half_rn(a.y)};
    h[1] = {__float2half_rn(a.z), __float2half_rn(a.w)};
    h[2] = {__float2half_rn(b.x), __float2half_rn(b.y)};
    h[3] = {__float2half_rn(b.z), __float2half_rn(b.w)};
    reinterpret_cast<uint4*>(xh)[i] = *reinterpret_cast<uint4*>(h);
}

struct PrepB { const float* W[6]; int K[6]; int N[6]; };
__global__ void k_prepB(PrepB p) {
    int b = blockIdx.x;
    const float* W = p.W[b];
    int K = p.K[b], N = p.N[b];
    for (int idx = threadIdx.x; idx < K * N; idx += blockDim.x) {
        int k = idx / N, n = idx % N;
        split_f16(W[idx], g_wth[b][n * K + k], g_wtl[b][n * K + k]);
    }
}

// ================= warp-per-node aggregation (fp16 gather) =================
__global__ __launch_bounds__(256, 8) void k_agg128(const __half* __restrict__ in,
                                                   __half* __restrict__ oh) {
    const int warp = threadIdx.x >> 5, lane = threadIdx.x & 31;
    const int n = blockIdx.x * 8 + warp;
    const int c4 = lane * 4;
    float dn = g_dinv[n];
    float acc0, acc1, acc2, acc3;
    {
        uint2 sv = *reinterpret_cast<const uint2*>(in + (size_t)n * 128 + c4);
        __half2 s0 = *reinterpret_cast<__half2*>(&sv.x);
        __half2 s1 = *reinterpret_cast<__half2*>(&sv.y);
        float w = dn * dn;
        acc0 = w * __half2float(s0.x); acc1 = w * __half2float(s0.y);
        acc2 = w * __half2float(s1.x); acc3 = w * __half2float(s1.y);
    }
    const int beg = g_rowptr[n], end = g_rowptr[n + 1];
    for (int base = beg; base < end; base += 32) {
        int cnt = end - base; if (cnt > 32) cnt = 32;
        int   col = 0; float wt = 0.0f;
        if (lane < cnt) { col = g_col[base + lane]; wt = g_wedge[base + lane]; }
        for (int j = 0; j < cnt; j++) {
            int   idx = __shfl_sync(0xFFFFFFFFu, col, j);
            float ww  = __shfl_sync(0xFFFFFFFFu, wt,  j);
            uint2 gv = *reinterpret_cast<const uint2*>(in + (size_t)idx * 128 + c4);
            __half2 g0 = *reinterpret_cast<__half2*>(&gv.x);
            __half2 g1 = *reinterpret_cast<__half2*>(&gv.y);
            acc0 += ww * __half2float(g0.x); acc1 += ww * __half2float(g0.y);
            acc2 += ww * __half2float(g1.x); acc3 += ww * __half2float(g1.y);
        }
    }
    __half2 o0 = {__float2half_rn(acc0), __float2half_rn(acc1)};
    __half2 o1 = {__float2half_rn(acc2), __float2half_rn(acc3)};
    *reinterpret_cast<uint2*>(oh + (size_t)n * 128 + c4) = make_uint2(
        *reinterpret_cast<uint32_t*>(&o0), *reinterpret_cast<uint32_t*>(&o1));
}

__global__ __launch_bounds__(256, 8) void k_agg256(const __half* __restrict__ in,
                                                   __half* __restrict__ oh) {
    const int warp = threadIdx.x >> 5, lane = threadIdx.x & 31;
    const int n = blockIdx.x * 8 + warp;
    const int c8 = lane * 8;
    float dn = g_dinv[n];
    float acc[8];
    {
        uint4 sv = *reinterpret_cast<const uint4*>(in + (size_t)n * 256 + c8);
        const __half2* sh = reinterpret_cast<const __half2*>(&sv);
        float w = dn * dn;
#pragma unroll
        for (int q = 0; q < 4; q++) {
            acc[2 * q]     = w * __half2float(sh[q].x);
            acc[2 * q + 1] = w * __half2float(sh[q].y);
        }
    }
    const int beg = g_rowptr[n], end = g_rowptr[n + 1];
    for (int base = beg; base < end; base += 32) {
        int cnt = end - base; if (cnt > 32) cnt = 32;
        int   col = 0; float wt = 0.0f;
        if (lane < cnt) { col = g_col[base + lane]; wt = g_wedge[base + lane]; }
        for (int j = 0; j < cnt; j++) {
            int   idx = __shfl_sync(0xFFFFFFFFu, col, j);
            float ww  = __shfl_sync(0xFFFFFFFFu, wt,  j);
            uint4 gv = *reinterpret_cast<const uint4*>(in + (size_t)idx * 256 + c8);
            const __half2* gh = reinterpret_cast<const __half2*>(&gv);
#pragma unroll
            for (int q = 0; q < 4; q++) {
                acc[2 * q]     += ww * __half2float(gh[q].x);
                acc[2 * q + 1] += ww * __half2float(gh[q].y);
            }
        }
    }
    __half2 hv[4];
#pragma unroll
    for (int q = 0; q < 4; q++)
        hv[q] = {__float2half_rn(acc[2 * q]), __float2half_rn(acc[2 * q + 1])};
    *reinterpret_cast<uint4*>(oh + (size_t)n * 256 + c8) = *reinterpret_cast<uint4*>(hv);
}

// ================= fp16 2-pass mma.sync GEMM (A unsplit, W split) =================
struct MJobs {
    const __half* A[3];
    const __half* Bh[3];
    const __half* Bl[3];
    const float*  bias[3];
    float*        C[3];
    __half*       Ch[3];
    int           lda[3];
    int           ldc[3];
    int           split[3];
};

template <int BM, int NN, int KK>
__global__ __launch_bounds__(256, 2) void k_mma(MJobs jobs, int do_relu) {
    extern __shared__ __align__(16) unsigned char smem[];
    constexpr int NCH = KK / 8;
    constexpr int AB  = BM * KK * 2;
    constexpr int BB  = NN * KK * 2;
    constexpr int NI  = NN / 32;
    constexpr int MI  = BM / 32;
    constexpr int KSTEPS = KK / 16;

    const int job = blockIdx.z;
    const int bm  = blockIdx.y * BM;
    const int tid = threadIdx.x;
    const int lane = tid & 31, warp = tid >> 5;
    const int wm = (warp >> 2) * (BM / 2);
    const int wn = (warp & 3) * (NN / 4);

    const __half* A = jobs.A[job];
    const int lda = jobs.lda[job];

    {
        const int ldach = lda / 8;
        uint4* s = reinterpret_cast<uint4*>(smem);
        for (int idx = tid; idx < BM * NCH; idx += 256) {
            int r = idx / NCH, cc = idx % NCH;
            long gr = bm + r; if (gr >= N_NODES) gr = N_NODES - 1;
            int sp = r * NCH + (cc ^ (r & 7));
            s[sp] = reinterpret_cast<const uint4*>(A)[gr * ldach + cc];
        }
        const uint4* bh = reinterpret_cast<const uint4*>(jobs.Bh[job]);
        const uint4* bl = reinterpret_cast<const uint4*>(jobs.Bl[job]);
        uint4* sb = reinterpret_cast<uint4*>(smem + AB);
        for (int idx = tid; idx < NN * NCH; idx += 256) {
            int r = idx / NCH, cc = idx % NCH;
            int sp = r * NCH + (cc ^ (r & 7));
            sb[sp]           = bh[idx];
            sb[sp + BB / 16] = bl[idx];
        }
    }
    __syncthreads();

    const uint32_t sbase = smem_u32(smem);
    const int group = lane >> 3, within = lane & 7;
    const int kaddA = group >> 1;
    uint32_t abyte[MI]; int rx[MI];
    {
        int mrow = wm + (group & 1) * 8 + within;
#pragma unroll
        for (int mi = 0; mi < MI; mi++) {
            int r = mrow + mi * 16;
            abyte[mi] = (uint32_t)(r * NCH) << 4;
            rx[mi] = r & 7;
        }
    }
    const int laneB = lane & 15;
    const int kaddB = laneB >> 3, withinB = laneB & 7;
    uint32_t bbyte[NI]; int nx[NI];
#pragma unroll
    for (int ni = 0; ni < NI; ni++) {
        int r = wn + ni * 8 + withinB;
        bbyte[ni] = (uint32_t)(r * NCH) << 4;
        nx[ni] = r & 7;
    }

    float acc[MI][NI][4];
#pragma unroll
    for (int mi = 0; mi < MI; mi++)
#pragma unroll
        for (int ni = 0; ni < NI; ni++)
#pragma unroll
            for (int q = 0; q < 4; q++) acc[mi][ni][q] = 0.0f;

#pragma unroll 1
    for (int pass = 0; pass < 2; pass++) {
        const uint32_t aoff = sbase;
        const uint32_t boff = sbase + AB + pass * BB;
#pragma unroll
        for (int s = 0; s < KSTEPS; s++) {
            const int kc = s * 2;
            uint32_t bf[NI][2];
#pragma unroll
            for (int ni = 0; ni < NI; ni++)
                ldsm_x2(bf[ni], boff + bbyte[ni] + ((uint32_t)((kc + kaddB) ^ nx[ni]) << 4));
#pragma unroll
            for (int mi = 0; mi < MI; mi++) {
                uint32_t af[4];
                ldsm_x4(af, aoff + abyte[mi] + ((uint32_t)((kc + kaddA) ^ rx[mi]) << 4));
#pragma unroll
                for (int ni = 0; ni < NI; ni++)
                    mma_f16(acc[mi][ni], af, bf[ni]);
            }
        }
    }

    const float* bias = jobs.bias[job];
    float* C = jobs.C[job];
    __half* Ch = jobs.Ch[job];
    const int ldc = jobs.ldc[job];
    const int splt = jobs.split[job];
    const int g = lane >> 2, tc = lane & 3;
#pragma unroll
    for (int mi = 0; mi < MI; mi++) {
#pragma unroll
        for (int ni = 0; ni < NI; ni++) {
            int n0 = wn + ni * 8 + tc * 2;
            float b0 = bias[n0], b1 = bias[n0 + 1];
            int m0 = bm + wm + mi * 16 + g;
            float v0 = acc[mi][ni][0] + b0, v1 = acc[mi][ni][1] + b1;
            float v2 = acc[mi][ni][2] + b0, v3 = acc[mi][ni][3] + b1;
            if (do_relu) {
                v0 = fmaxf(v0, 0.0f); v1 = fmaxf(v1, 0.0f);
                v2 = fmaxf(v2, 0.0f); v3 = fmaxf(v3, 0.0f);
            }
            if (splt) {
                if (m0 < N_NODES)
                    *reinterpret_cast<__half2*>(Ch + (size_t)m0 * ldc + n0) =
                        __half2{__float2half_rn(v0), __float2half_rn(v1)};
                if (m0 + 8 < N_NODES)
                    *reinterpret_cast<__half2*>(Ch + (size_t)(m0 + 8) * ldc + n0) =
                        __half2{__float2half_rn(v2), __float2half_rn(v3)};
            } else {
                if (m0 < N_NODES)
                    *reinterpret_cast<float2*>(C + (size_t)m0 * ldc + n0) = make_float2(v0, v1);
                if (m0 + 8 < N_NODES)
                    *reinterpret_cast<float2*>(C + (size_t)(m0 + 8) * ldc + n0) = make_float2(v2, v3);
            }
        }
    }
}

// ================= attention fusion =================
__global__ void k_attn(const float* __restrict__ watt, const float* __restrict__ batt) {
    const int half = threadIdx.x >> 7;
    const int c = threadIdx.x & 127;
    const int n = blockIdx.x * 2 + half;
    float h1v = g_h1[n * 128 + c];
    float h2v = g_h2[n * 128 + c];
    float wa = watt[c];
    float p1 = h1v * wa;
    float p2 = h2v * wa;
#pragma unroll
    for (int o = 16; o > 0; o >>= 1) {
        p1 += __shfl_down_sync(0xFFFFFFFFu, p1, o);
        p2 += __shfl_down_sync(0xFFFFFFFFu, p2, o);
    }
    __shared__ float s1[8], s2[8];
    __shared__ float a1s[2];
    int w = threadIdx.x >> 5;
    if ((threadIdx.x & 31) == 0) { s1[w] = p1; s2[w] = p2; }
    __syncthreads();
    if (c == 0) {
        int b = half * 4;
        float S1 = s1[b] + s1[b+1] + s1[b+2] + s1[b+3] + batt[0];
        float S2 = s2[b] + s2[b+1] + s2[b+2] + s2[b+3] + batt[0];
        a1s[half] = 1.0f / (1.0f + expf(S2 - S1));
    }
    __syncthreads();
    float a1 = a1s[half];
    float v = a1 * h1v + (1.0f - a1) * h2v;
    g_comb[n * 256 + 128 + c] = __float2half_rn(v);
}

// ================= launch =================
extern "C" void kernel_launch(void* const* d_in, const int* in_sizes, int n_in,
                              void* d_out, int out_size) {
    const float* x    = (const float*)d_in[0];
    const int*   ei32 = (const int*)d_in[1];
    const float* W_s1 = (const float*)d_in[2];
    const float* b_s1 = (const float*)d_in[3];
    const float* W_s2 = (const float*)d_in[4];
    const float* b_s2 = (const float*)d_in[5];
    const float* W_m1 = (const float*)d_in[6];
    const float* b_m1 = (const float*)d_in[7];
    const float* W_m21 = (const float*)d_in[8];
    const float* b_m21 = (const float*)d_in[9];
    const float* W_m22 = (const float*)d_in[10];
    const float* b_m22 = (const float*)d_in[11];
    const float* W_att = (const float*)d_in[12];
    const float* b_att = (const float*)d_in[13];
    const float* W_fc  = (const float*)d_in[14];
    const float* b_fc  = (const float*)d_in[15];
    float* out = (float*)d_out;

    float* h1;   cudaGetSymbolAddress((void**)&h1, g_h1);
    float* h2;   cudaGetSymbolAddress((void**)&h2, g_h2);
    __half *xh, *bufA, *aggx, *agg2, *comb, *wth, *wtl;
    cudaGetSymbolAddress((void**)&xh, g_xh);
    cudaGetSymbolAddress((void**)&bufA, g_bufA);
    cudaGetSymbolAddress((void**)&aggx, g_aggx);
    cudaGetSymbolAddress((void**)&agg2, g_agg2);
    cudaGetSymbolAddress((void**)&comb, g_comb);
    cudaGetSymbolAddress((void**)&wth, g_wth);
    cudaGetSymbolAddress((void**)&wtl, g_wtl);

    // layer GEMMs: BM=128, NN=128, KK=128: A 32KB + B 2x32KB = 96KB -> occ 2
    const int SM_L  = 128 * 128 * 2 + 2 * (128 * 128 * 2);  // 98304
    const int SM_FC = 64 * 256 * 2 + 2 * (64 * 256 * 2);    // 98304, occ 2
    static bool attr_done = false;
    if (!attr_done) {
        cudaFuncSetAttribute(k_mma<128, 128, 128>, cudaFuncAttributeMaxDynamicSharedMemorySize, SM_L);
        cudaFuncSetAttribute(k_mma<64, 64, 256>,   cudaFuncAttributeMaxDynamicSharedMemorySize, SM_FC);
        attr_done = true;
    }

    const int TB = 256;
    k_detect_init<<<(N_NODES + TB - 1) / TB, TB>>>(ei32);
    k_count<<<(N_EDGES + TB - 1) / TB, TB>>>(ei32);
    k_scan_dinv<<<1, 1024>>>();
    k_fill<<<(N_EDGES + TB - 1) / TB, TB>>>(ei32);
    k_convx<<<(N_NODES * 128 / 8 + TB - 1) / TB, TB>>>(x, xh);

    {
        PrepB p;
        p.W[0] = W_s1;  p.K[0] = 128; p.N[0] = 128;
        p.W[1] = W_m21; p.K[1] = 128; p.N[1] = 128;
        p.W[2] = W_m1;  p.K[2] = 128; p.N[2] = 128;
        p.W[3] = W_s2;  p.K[3] = 128; p.N[3] = 128;
        p.W[4] = W_m22; p.K[4] = 128; p.N[4] = 128;
        p.W[5] = W_fc;  p.K[5] = 256; p.N[5] = 64;
        k_prepB<<<6, 256>>>(p);
    }

    k_agg128<<<N_NODES / 8, 256>>>(xh, aggx);

    const int MT128 = (N_NODES + 127) / 128;  // 391
    const int MT64  = (N_NODES + 63) / 64;    // 782

    {
        MJobs j = {};
        for (int q = 0; q < 3; q++) { j.A[q] = aggx; j.lda[q] = 128; }
        j.Bh[0] = wth + 0 * 16384; j.Bl[0] = wtl + 0 * 16384; j.bias[0] = b_s1;
        j.Ch[0] = bufA;       j.ldc[0] = 256; j.split[0] = 1;
        j.Bh[1] = wth + 1 * 16384; j.Bl[1] = wtl + 1 * 16384; j.bias[1] = b_m21;
        j.Ch[1] = bufA + 128; j.ldc[1] = 256; j.split[1] = 1;
        j.Bh[2] = wth + 2 * 16384; j.Bl[2] = wtl + 2 * 16384; j.bias[2] = b_m1;
        j.C[2] = h1; j.ldc[2] = 128; j.split[2] = 0;
        k_mma<128, 128, 128><<<dim3(1, MT128, 3), 256, SM_L>>>(j, 1);
    }

    k_agg256<<<N_NODES / 8, 256>>>(bufA, agg2);

    {
        MJobs j = {};
        j.A[0] = agg2;       j.lda[0] = 256;
        j.A[1] = agg2 + 128; j.lda[1] = 256;
        j.A[2] = j.A[0];     j.lda[2] = 256;
        j.Bh[0] = wth + 3 * 16384; j.Bl[0] = wtl + 3 * 16384; j.bias[0] = b_s2;
        j.Ch[0] = comb; j.ldc[0] = 256; j.split[0] = 1;
        j.Bh[1] = wth + 4 * 16384; j.Bl[1] = wtl + 4 * 16384; j.bias[1] = b_m22;
        j.C[1] = h2; j.ldc[1] = 128; j.split[1] = 0;
        j.Bh[2] = j.Bh[0]; j.Bl[2] = j.Bl[0]; j.bias[2] = j.bias[0];
        j.Ch[2] = j.Ch[0]; j.ldc[2] = j.ldc[0]; j.split[2] = 1;
        k_mma<128, 128, 128><<<dim3(1, MT128, 2), 256, SM_L>>>(j, 1);
    }

    k_attn<<<N_NODES / 2, 256>>>(W_att, b_att);

    {
        MJobs j = {};
        for (int q = 0; q < 3; q++) {
            j.A[q] = comb; j.lda[q] = 256;
            j.Bh[q] = wth + 5 * 16384; j.Bl[q] = wtl + 5 * 16384;
            j.bias[q] = b_fc; j.C[q] = out; j.ldc[q] = 64; j.split[q] = 0;
        }
        k_mma<64, 64, 256><<<dim3(1, MT64, 1), 256, SM_FC>>>(j, 0);
    }

    (void)in_sizes; (void)n_in; (void)out_size;
}

// round 13
// speedup vs baseline: 1.3062x; 1.0062x over previous
#include <cuda_runtime.h>
#include <cuda_fp16.h>
#include <math.h>
#include <cstdint>

#define N_NODES 50000
#define N_EDGES 800000

// ================= scratch =================
__device__ int   g_is64;
__device__ int   g_edeg[N_NODES];
__device__ float g_dinv[N_NODES];
__device__ int   g_rowptr[N_NODES + 1];
__device__ int   g_cursor[N_NODES];
__device__ int   g_col[N_EDGES];
__device__ float g_wedge[N_EDGES];

__device__ float g_h1[N_NODES * 128];
__device__ float g_h2[N_NODES * 128];

// fp16 buffers
__device__ __half g_xh[N_NODES * 128];
__device__ __half g_bufA[N_NODES * 256];
__device__ __half g_aggx[N_NODES * 128];
__device__ __half g_agg2[N_NODES * 256];
__device__ __half g_comb[N_NODES * 256];
__device__ __half g_wth[6][16384];
__device__ __half g_wtl[6][16384];

// ================= helpers =================
__device__ __forceinline__ uint32_t smem_u32(const void* p) {
    uint32_t a;
    asm("{ .reg .u64 t; cvta.to.shared.u64 t, %1; cvt.u32.u64 %0, t; }" : "=r"(a) : "l"(p));
    return a;
}
__device__ __forceinline__ void ldsm_x4(uint32_t* r, uint32_t addr) {
    asm volatile("ldmatrix.sync.aligned.m8n8.x4.shared.b16 {%0,%1,%2,%3}, [%4];"
                 : "=r"(r[0]), "=r"(r[1]), "=r"(r[2]), "=r"(r[3]) : "r"(addr));
}
__device__ __forceinline__ void ldsm_x2(uint32_t* r, uint32_t addr) {
    asm volatile("ldmatrix.sync.aligned.m8n8.x2.shared.b16 {%0,%1}, [%2];"
                 : "=r"(r[0]), "=r"(r[1]) : "r"(addr));
}
__device__ __forceinline__ void mma_f16(float* d, const uint32_t* a, const uint32_t* b) {
    asm volatile("mma.sync.aligned.m16n8k16.row.col.f32.f16.f16.f32 "
                 "{%0,%1,%2,%3}, {%4,%5,%6,%7}, {%8,%9}, {%0,%1,%2,%3};"
                 : "+f"(d[0]), "+f"(d[1]), "+f"(d[2]), "+f"(d[3])
                 : "r"(a[0]), "r"(a[1]), "r"(a[2]), "r"(a[3]), "r"(b[0]), "r"(b[1]));
}
__device__ __forceinline__ void split_f16(float v, __half& h, __half& l) {
    __half hb = __float2half_rn(v);
    h = hb;
    l = __float2half_rn(v - __half2float(hb));
}

// ================= fused detect + edeg zero =================
__global__ void k_detect_init(const int* __restrict__ ei32) {
    int i = blockIdx.x * blockDim.x + threadIdx.x;
    if (i < N_NODES) g_edeg[i] = 0;
    if (blockIdx.x == 0) {
        __shared__ int nz;
        if (threadIdx.x == 0) nz = 0;
        __syncthreads();
        int local = 0;
        for (int q = threadIdx.x; q < 2048; q += blockDim.x)
            if (ei32[2 * q + 1] != 0) local = 1;
        if (local) atomicOr(&nz, 1);
        __syncthreads();
        if (threadIdx.x == 0) g_is64 = nz ? 0 : 1;
    }
}

__global__ void k_count(const int* __restrict__ ei32) {
    int e = blockIdx.x * blockDim.x + threadIdx.x;
    if (e < N_EDGES) {
        int d = g_is64 ? ei32[2 * (N_EDGES + e)] : ei32[N_EDGES + e];
        atomicAdd(&g_edeg[d], 1);
    }
}

__global__ void k_scan_dinv() {
    __shared__ int part[1024];
    const int t = threadIdx.x;
    const int CH = (N_NODES + 1023) / 1024;
    int start = t * CH;
    int s = 0;
    for (int i = 0; i < CH; i++) { int idx = start + i; if (idx < N_NODES) s += g_edeg[idx]; }
    part[t] = s;
    __syncthreads();
    for (int off = 1; off < 1024; off <<= 1) {
        int v = (t >= off) ? part[t - off] : 0;
        __syncthreads();
        part[t] += v;
        __syncthreads();
    }
    int run = (t == 0) ? 0 : part[t - 1];
    for (int i = 0; i < CH; i++) {
        int idx = start + i;
        if (idx < N_NODES) {
            g_rowptr[idx] = run;
            g_cursor[idx] = run;
            g_dinv[idx] = rsqrtf((float)(g_edeg[idx] + 1));
            run += g_edeg[idx];
        }
    }
    if (t == 1023) g_rowptr[N_NODES] = run;
}

__global__ void k_fill(const int* __restrict__ ei32) {
    int e = blockIdx.x * blockDim.x + threadIdx.x;
    if (e < N_EDGES) {
        int s, d;
        if (g_is64) { s = ei32[2 * e]; d = ei32[2 * (N_EDGES + e)]; }
        else        { s = ei32[e];     d = ei32[N_EDGES + e]; }
        int p = atomicAdd(&g_cursor[d], 1);
        g_col[p] = s;
        g_wedge[p] = g_dinv[s] * g_dinv[d];
    }
}

__global__ void k_convx(const float* __restrict__ x, __half* __restrict__ xh) {
    int i = blockIdx.x * blockDim.x + threadIdx.x;
    const float4* xp = reinterpret_cast<const float4*>(x) + 2 * (size_t)i;
    float4 a = xp[0], b = xp[1];
    __half2 h[4];
    h[0] = {__float2half_rn(a.x), __float2half_rn(a.y)};
    h[1] = {__float2half_rn(a.z), __float2half_rn(a.w)};
    h[2] = {__float2half_rn(b.x), __float2half_rn(b.y)};
    h[3] = {__float2half_rn(b.z), __float2half_rn(b.w)};
    reinterpret_cast<uint4*>(xh)[i] = *reinterpret_cast<uint4*>(h);
}

struct PrepB { const float* W[6]; int K[6]; int N[6]; };
__global__ void k_prepB(PrepB p) {
    int b = blockIdx.x;
    const float* W = p.W[b];
    int K = p.K[b], N = p.N[b];
    for (int idx = threadIdx.x; idx < K * N; idx += blockDim.x) {
        int k = idx / N, n = idx % N;
        split_f16(W[idx], g_wth[b][n * K + k], g_wtl[b][n * K + k]);
    }
}

// ================= warp-per-node aggregation (fp16 gather) =================
__global__ __launch_bounds__(256, 8) void k_agg128(const __half* __restrict__ in,
                                                   __half* __restrict__ oh) {
    const int warp = threadIdx.x >> 5, lane = threadIdx.x & 31;
    const int n = blockIdx.x * 8 + warp;
    const int c4 = lane * 4;
    float dn = g_dinv[n];
    float acc0, acc1, acc2, acc3;
    {
        uint2 sv = *reinterpret_cast<const uint2*>(in + (size_t)n * 128 + c4);
        __half2 s0 = *reinterpret_cast<__half2*>(&sv.x);
        __half2 s1 = *reinterpret_cast<__half2*>(&sv.y);
        float w = dn * dn;
        acc0 = w * __half2float(s0.x); acc1 = w * __half2float(s0.y);
        acc2 = w * __half2float(s1.x); acc3 = w * __half2float(s1.y);
    }
    const int beg = g_rowptr[n], end = g_rowptr[n + 1];
    for (int base = beg; base < end; base += 32) {
        int cnt = end - base; if (cnt > 32) cnt = 32;
        int   col = 0; float wt = 0.0f;
        if (lane < cnt) { col = g_col[base + lane]; wt = g_wedge[base + lane]; }
        for (int j = 0; j < cnt; j++) {
            int   idx = __shfl_sync(0xFFFFFFFFu, col, j);
            float ww  = __shfl_sync(0xFFFFFFFFu, wt,  j);
            uint2 gv = *reinterpret_cast<const uint2*>(in + (size_t)idx * 128 + c4);
            __half2 g0 = *reinterpret_cast<__half2*>(&gv.x);
            __half2 g1 = *reinterpret_cast<__half2*>(&gv.y);
            acc0 += ww * __half2float(g0.x); acc1 += ww * __half2float(g0.y);
            acc2 += ww * __half2float(g1.x); acc3 += ww * __half2float(g1.y);
        }
    }
    __half2 o0 = {__float2half_rn(acc0), __float2half_rn(acc1)};
    __half2 o1 = {__float2half_rn(acc2), __float2half_rn(acc3)};
    *reinterpret_cast<uint2*>(oh + (size_t)n * 128 + c4) = make_uint2(
        *reinterpret_cast<uint32_t*>(&o0), *reinterpret_cast<uint32_t*>(&o1));
}

__global__ __launch_bounds__(256, 8) void k_agg256(const __half* __restrict__ in,
                                                   __half* __restrict__ oh) {
    const int warp = threadIdx.x >> 5, lane = threadIdx.x & 31;
    const int n = blockIdx.x * 8 + warp;
    const int c8 = lane * 8;
    float dn = g_dinv[n];
    float acc[8];
    {
        uint4 sv = *reinterpret_cast<const uint4*>(in + (size_t)n * 256 + c8);
        const __half2* sh = reinterpret_cast<const __half2*>(&sv);
        float w = dn * dn;
#pragma unroll
        for (int q = 0; q < 4; q++) {
            acc[2 * q]     = w * __half2float(sh[q].x);
            acc[2 * q + 1] = w * __half2float(sh[q].y);
        }
    }
    const int beg = g_rowptr[n], end = g_rowptr[n + 1];
    for (int base = beg; base < end; base += 32) {
        int cnt = end - base; if (cnt > 32) cnt = 32;
        int   col = 0; float wt = 0.0f;
        if (lane < cnt) { col = g_col[base + lane]; wt = g_wedge[base + lane]; }
        for (int j = 0; j < cnt; j++) {
            int   idx = __shfl_sync(0xFFFFFFFFu, col, j);
            float ww  = __shfl_sync(0xFFFFFFFFu, wt,  j);
            uint4 gv = *reinterpret_cast<const uint4*>(in + (size_t)idx * 256 + c8);
            const __half2* gh = reinterpret_cast<const __half2*>(&gv);
#pragma unroll
            for (int q = 0; q < 4; q++) {
                acc[2 * q]     += ww * __half2float(gh[q].x);
                acc[2 * q + 1] += ww * __half2float(gh[q].y);
            }
        }
    }
    __half2 hv[4];
#pragma unroll
    for (int q = 0; q < 4; q++)
        hv[q] = {__float2half_rn(acc[2 * q]), __float2half_rn(acc[2 * q + 1])};
    *reinterpret_cast<uint4*>(oh + (size_t)n * 256 + c8) = *reinterpret_cast<uint4*>(hv);
}

// ================= fp16 2-pass mma.sync GEMM =================
// THREADS=512: 16 warps in a 4m x 4n grid (warp tile BM/4 x NN/4)
// THREADS=256: 8 warps in a 2m x 4n grid (warp tile BM/2 x NN/4)
struct MJobs {
    const __half* A[3];
    const __half* Bh[3];
    const __half* Bl[3];
    const float*  bias[3];
    float*        C[3];
    __half*       Ch[3];
    int           lda[3];
    int           ldc[3];
    int           split[3];
};

template <int THREADS, int BM, int NN, int KK>
__global__ __launch_bounds__(THREADS, 2) void k_mma(MJobs jobs, int do_relu) {
    extern __shared__ __align__(16) unsigned char smem[];
    constexpr int NCH = KK / 8;
    constexpr int AB  = BM * KK * 2;
    constexpr int BB  = NN * KK * 2;
    constexpr int MWARPS = (THREADS == 512) ? 4 : 2;
    constexpr int MI  = BM / MWARPS / 16;
    constexpr int NI  = NN / 4 / 8;
    constexpr int KSTEPS = KK / 16;

    const int job = blockIdx.z;
    const int bm  = blockIdx.y * BM;
    const int tid = threadIdx.x;
    const int lane = tid & 31, warp = tid >> 5;
    const int wm = (warp >> 2) * (BM / MWARPS);
    const int wn = (warp & 3) * (NN / 4);

    const __half* A = jobs.A[job];
    const int lda = jobs.lda[job];

    {
        const int ldach = lda / 8;
        uint4* s = reinterpret_cast<uint4*>(smem);
        for (int idx = tid; idx < BM * NCH; idx += THREADS) {
            int r = idx / NCH, cc = idx % NCH;
            long gr = bm + r; if (gr >= N_NODES) gr = N_NODES - 1;
            int sp = r * NCH + (cc ^ (r & 7));
            s[sp] = reinterpret_cast<const uint4*>(A)[gr * ldach + cc];
        }
        const uint4* bh = reinterpret_cast<const uint4*>(jobs.Bh[job]);
        const uint4* bl = reinterpret_cast<const uint4*>(jobs.Bl[job]);
        uint4* sb = reinterpret_cast<uint4*>(smem + AB);
        for (int idx = tid; idx < NN * NCH; idx += THREADS) {
            int r = idx / NCH, cc = idx % NCH;
            int sp = r * NCH + (cc ^ (r & 7));
            sb[sp]           = bh[idx];
            sb[sp + BB / 16] = bl[idx];
        }
    }
    __syncthreads();

    const uint32_t sbase = smem_u32(smem);
    const int group = lane >> 3, within = lane & 7;
    const int kaddA = group >> 1;
    uint32_t abyte[MI]; int rx[MI];
    {
        int mrow = wm + (group & 1) * 8 + within;
#pragma unroll
        for (int mi = 0; mi < MI; mi++) {
            int r = mrow + mi * 16;
            abyte[mi] = (uint32_t)(r * NCH) << 4;
            rx[mi] = r & 7;
        }
    }
    const int laneB = lane & 15;
    const int kaddB = laneB >> 3, withinB = laneB & 7;
    uint32_t bbyte[NI]; int nx[NI];
#pragma unroll
    for (int ni = 0; ni < NI; ni++) {
        int r = wn + ni * 8 + withinB;
        bbyte[ni] = (uint32_t)(r * NCH) << 4;
        nx[ni] = r & 7;
    }

    float acc[MI][NI][4];
#pragma unroll
    for (int mi = 0; mi < MI; mi++)
#pragma unroll
        for (int ni = 0; ni < NI; ni++)
#pragma unroll
            for (int q = 0; q < 4; q++) acc[mi][ni][q] = 0.0f;

#pragma unroll 1
    for (int pass = 0; pass < 2; pass++) {
        const uint32_t aoff = sbase;
        const uint32_t boff = sbase + AB + pass * BB;
#pragma unroll
        for (int s = 0; s < KSTEPS; s++) {
            const int kc = s * 2;
            uint32_t bf[NI][2];
#pragma unroll
            for (int ni = 0; ni < NI; ni++)
                ldsm_x2(bf[ni], boff + bbyte[ni] + ((uint32_t)((kc + kaddB) ^ nx[ni]) << 4));
#pragma unroll
            for (int mi = 0; mi < MI; mi++) {
                uint32_t af[4];
                ldsm_x4(af, aoff + abyte[mi] + ((uint32_t)((kc + kaddA) ^ rx[mi]) << 4));
#pragma unroll
                for (int ni = 0; ni < NI; ni++)
                    mma_f16(acc[mi][ni], af, bf[ni]);
            }
        }
    }

    const float* bias = jobs.bias[job];
    float* C = jobs.C[job];
    __half* Ch = jobs.Ch[job];
    const int ldc = jobs.ldc[job];
    const int splt = jobs.split[job];
    const int g = lane >> 2, tc = lane & 3;
#pragma unroll
    for (int mi = 0; mi < MI; mi++) {
#pragma unroll
        for (int ni = 0; ni < NI; ni++) {
            int n0 = wn + ni * 8 + tc * 2;
            float b0 = bias[n0], b1 = bias[n0 + 1];
            int m0 = bm + wm + mi * 16 + g;
            float v0 = acc[mi][ni][0] + b0, v1 = acc[mi][ni][1] + b1;
            float v2 = acc[mi][ni][2] + b0, v3 = acc[mi][ni][3] + b1;
            if (do_relu) {
                v0 = fmaxf(v0, 0.0f); v1 = fmaxf(v1, 0.0f);
                v2 = fmaxf(v2, 0.0f); v3 = fmaxf(v3, 0.0f);
            }
            if (splt) {
                if (m0 < N_NODES)
                    *reinterpret_cast<__half2*>(Ch + (size_t)m0 * ldc + n0) =
                        __half2{__float2half_rn(v0), __float2half_rn(v1)};
                if (m0 + 8 < N_NODES)
                    *reinterpret_cast<__half2*>(Ch + (size_t)(m0 + 8) * ldc + n0) =
                        __half2{__float2half_rn(v2), __float2half_rn(v3)};
            } else {
                if (m0 < N_NODES)
                    *reinterpret_cast<float2*>(C + (size_t)m0 * ldc + n0) = make_float2(v0, v1);
                if (m0 + 8 < N_NODES)
                    *reinterpret_cast<float2*>(C + (size_t)(m0 + 8) * ldc + n0) = make_float2(v2, v3);
            }
        }
    }
}

// ================= attention fusion =================
__global__ void k_attn(const float* __restrict__ watt, const float* __restrict__ batt) {
    const int half = threadIdx.x >> 7;
    const int c = threadIdx.x & 127;
    const int n = blockIdx.x * 2 + half;
    float h1v = g_h1[n * 128 + c];
    float h2v = g_h2[n * 128 + c];
    float wa = watt[c];
    float p1 = h1v * wa;
    float p2 = h2v * wa;
#pragma unroll
    for (int o = 16; o > 0; o >>= 1) {
        p1 += __shfl_down_sync(0xFFFFFFFFu, p1, o);
        p2 += __shfl_down_sync(0xFFFFFFFFu, p2, o);
    }
    __shared__ float s1[8], s2[8];
    __shared__ float a1s[2];
    int w = threadIdx.x >> 5;
    if ((threadIdx.x & 31) == 0) { s1[w] = p1; s2[w] = p2; }
    __syncthreads();
    if (c == 0) {
        int b = half * 4;
        float S1 = s1[b] + s1[b+1] + s1[b+2] + s1[b+3] + batt[0];
        float S2 = s2[b] + s2[b+1] + s2[b+2] + s2[b+3] + batt[0];
        a1s[half] = 1.0f / (1.0f + expf(S2 - S1));
    }
    __syncthreads();
    float a1 = a1s[half];
    float v = a1 * h1v + (1.0f - a1) * h2v;
    g_comb[n * 256 + 128 + c] = __float2half_rn(v);
}

// ================= launch =================
extern "C" void kernel_launch(void* const* d_in, const int* in_sizes, int n_in,
                              void* d_out, int out_size) {
    const float* x    = (const float*)d_in[0];
    const int*   ei32 = (const int*)d_in[1];
    const float* W_s1 = (const float*)d_in[2];
    const float* b_s1 = (const float*)d_in[3];
    const float* W_s2 = (const float*)d_in[4];
    const float* b_s2 = (const float*)d_in[5];
    const float* W_m1 = (const float*)d_in[6];
    const float* b_m1 = (const float*)d_in[7];
    const float* W_m21 = (const float*)d_in[8];
    const float* b_m21 = (const float*)d_in[9];
    const float* W_m22 = (const float*)d_in[10];
    const float* b_m22 = (const float*)d_in[11];
    const float* W_att = (const float*)d_in[12];
    const float* b_att = (const float*)d_in[13];
    const float* W_fc  = (const float*)d_in[14];
    const float* b_fc  = (const float*)d_in[15];
    float* out = (float*)d_out;

    float* h1;   cudaGetSymbolAddress((void**)&h1, g_h1);
    float* h2;   cudaGetSymbolAddress((void**)&h2, g_h2);
    __half *xh, *bufA, *aggx, *agg2, *comb, *wth, *wtl;
    cudaGetSymbolAddress((void**)&xh, g_xh);
    cudaGetSymbolAddress((void**)&bufA, g_bufA);
    cudaGetSymbolAddress((void**)&aggx, g_aggx);
    cudaGetSymbolAddress((void**)&agg2, g_agg2);
    cudaGetSymbolAddress((void**)&comb, g_comb);
    cudaGetSymbolAddress((void**)&wth, g_wth);
    cudaGetSymbolAddress((void**)&wtl, g_wtl);

    const int SM_L  = 128 * 128 * 2 + 2 * (128 * 128 * 2);  // 98304, occ 2, 512 thr
    const int SM_FC = 64 * 256 * 2 + 2 * (64 * 256 * 2);    // 98304, occ 2, 256 thr
    static bool attr_done = false;
    if (!attr_done) {
        cudaFuncSetAttribute(k_mma<512, 128, 128, 128>, cudaFuncAttributeMaxDynamicSharedMemorySize, SM_L);
        cudaFuncSetAttribute(k_mma<256, 64, 64, 256>,   cudaFuncAttributeMaxDynamicSharedMemorySize, SM_FC);
        attr_done = true;
    }

    const int TB = 256;
    k_detect_init<<<(N_NODES + TB - 1) / TB, TB>>>(ei32);
    k_count<<<(N_EDGES + TB - 1) / TB, TB>>>(ei32);
    k_scan_dinv<<<1, 1024>>>();
    k_fill<<<(N_EDGES + TB - 1) / TB, TB>>>(ei32);
    k_convx<<<(N_NODES * 128 / 8 + TB - 1) / TB, TB>>>(x, xh);

    {
        PrepB p;
        p.W[0] = W_s1;  p.K[0] = 128; p.N[0] = 128;
        p.W[1] = W_m21; p.K[1] = 128; p.N[1] = 128;
        p.W[2] = W_m1;  p.K[2] = 128; p.N[2] = 128;
        p.W[3] = W_s2;  p.K[3] = 128; p.N[3] = 128;
        p.W[4] = W_m22; p.K[4] = 128; p.N[4] = 128;
        p.W[5] = W_fc;  p.K[5] = 256; p.N[5] = 64;
        k_prepB<<<6, 256>>>(p);
    }

    k_agg128<<<N_NODES / 8, 256>>>(xh, aggx);

    const int MT128 = (N_NODES + 127) / 128;  // 391
    const int MT64  = (N_NODES + 63) / 64;    // 782

    {
        MJobs j = {};
        for (int q = 0; q < 3; q++) { j.A[q] = aggx; j.lda[q] = 128; }
        j.Bh[0] = wth + 0 * 16384; j.Bl[0] = wtl + 0 * 16384; j.bias[0] = b_s1;
        j.Ch[0] = bufA;       j.ldc[0] = 256; j.split[0] = 1;
        j.Bh[1] = wth + 1 * 16384; j.Bl[1] = wtl + 1 * 16384; j.bias[1] = b_m21;
        j.Ch[1] = bufA + 128; j.ldc[1] = 256; j.split[1] = 1;
        j.Bh[2] = wth + 2 * 16384; j.Bl[2] = wtl + 2 * 16384; j.bias[2] = b_m1;
        j.C[2] = h1; j.ldc[2] = 128; j.split[2] = 0;
        k_mma<512, 128, 128, 128><<<dim3(1, MT128, 3), 512, SM_L>>>(j, 1);
    }

    k_agg256<<<N_NODES / 8, 256>>>(bufA, agg2);

    {
        MJobs j = {};
        j.A[0] = agg2;       j.lda[0] = 256;
        j.A[1] = agg2 + 128; j.lda[1] = 256;
        j.A[2] = j.A[0];     j.lda[2] = 256;
        j.Bh[0] = wth + 3 * 16384; j.Bl[0] = wtl + 3 * 16384; j.bias[0] = b_s2;
        j.Ch[0] = comb; j.ldc[0] = 256; j.split[0] = 1;
        j.Bh[1] = wth + 4 * 16384; j.Bl[1] = wtl + 4 * 16384; j.bias[1] = b_m22;
        j.C[1] = h2; j.ldc[1] = 128; j.split[1] = 0;
        j.Bh[2] = j.Bh[0]; j.Bl[2] = j.Bl[0]; j.bias[2] = j.bias[0];
        j.Ch[2] = j.Ch[0]; j.ldc[2] = j.ldc[0]; j.split[2] = 1;
        k_mma<512, 128, 128, 128><<<dim3(1, MT128, 2), 512, SM_L>>>(j, 1);
    }

    k_attn<<<N_NODES / 2, 256>>>(W_att, b_att);

    {
        MJobs j = {};
        for (int q = 0; q < 3; q++) {
            j.A[q] = comb; j.lda[q] = 256;
            j.Bh[q] = wth + 5 * 16384; j.Bl[q] = wtl + 5 * 16384;
            j.bias[q] = b_fc; j.C[q] = out; j.ldc[q] = 64; j.split[q] = 0;
        }
        k_mma<256, 64, 64, 256><<<dim3(1, MT64, 1), 256, SM_FC>>>(j, 0);
    }

    (void)in_sizes; (void)n_in; (void)out_size;
}

// round 14
// speedup vs baseline: 1.3340x; 1.0213x over previous
#include <cuda_runtime.h>
#include <cuda_fp16.h>
#include <math.h>
#include <cstdint>

#define N_NODES 50000
#define N_EDGES 800000

// ================= scratch =================
__device__ int   g_is64;
__device__ int   g_edeg[N_NODES];
__device__ float g_dinv[N_NODES];
__device__ int   g_rowptr[N_NODES + 1];
__device__ int   g_cursor[N_NODES];
__device__ int   g_col[N_EDGES];
__device__ float g_wedge[N_EDGES];

// fp16 buffers
__device__ __half g_h1[N_NODES * 128];
__device__ __half g_h2[N_NODES * 128];
__device__ __half g_xh[N_NODES * 128];
__device__ __half g_bufA[N_NODES * 256];
__device__ __half g_aggx[N_NODES * 128];
__device__ __half g_agg2[N_NODES * 256];
__device__ __half g_comb[N_NODES * 256];
__device__ __half g_wth[6][16384];
__device__ __half g_wtl[6][16384];

// ================= helpers =================
__device__ __forceinline__ uint32_t smem_u32(const void* p) {
    uint32_t a;
    asm("{ .reg .u64 t; cvta.to.shared.u64 t, %1; cvt.u32.u64 %0, t; }" : "=r"(a) : "l"(p));
    return a;
}
__device__ __forceinline__ void ldsm_x4(uint32_t* r, uint32_t addr) {
    asm volatile("ldmatrix.sync.aligned.m8n8.x4.shared.b16 {%0,%1,%2,%3}, [%4];"
                 : "=r"(r[0]), "=r"(r[1]), "=r"(r[2]), "=r"(r[3]) : "r"(addr));
}
__device__ __forceinline__ void ldsm_x2(uint32_t* r, uint32_t addr) {
    asm volatile("ldmatrix.sync.aligned.m8n8.x2.shared.b16 {%0,%1}, [%2];"
                 : "=r"(r[0]), "=r"(r[1]) : "r"(addr));
}
__device__ __forceinline__ void mma_f16(float* d, const uint32_t* a, const uint32_t* b) {
    asm volatile("mma.sync.aligned.m16n8k16.row.col.f32.f16.f16.f32 "
                 "{%0,%1,%2,%3}, {%4,%5,%6,%7}, {%8,%9}, {%0,%1,%2,%3};"
                 : "+f"(d[0]), "+f"(d[1]), "+f"(d[2]), "+f"(d[3])
                 : "r"(a[0]), "r"(a[1]), "r"(a[2]), "r"(a[3]), "r"(b[0]), "r"(b[1]));
}
__device__ __forceinline__ void split_f16(float v, __half& h, __half& l) {
    __half hb = __float2half_rn(v);
    h = hb;
    l = __float2half_rn(v - __half2float(hb));
}

// ================= fused: detect + edeg zero + weight prep =================
struct PrepB { const float* W[6]; int K[6]; int N[6]; };
__global__ void k_detect_init_prep(const int* __restrict__ ei32, PrepB p, int nInitBlocks) {
    if ((int)blockIdx.x < nInitBlocks) {
        int i = blockIdx.x * blockDim.x + threadIdx.x;
        if (i < N_NODES) g_edeg[i] = 0;
        if (blockIdx.x == 0) {
            __shared__ int nz;
            if (threadIdx.x == 0) nz = 0;
            __syncthreads();
            int local = 0;
            for (int q = threadIdx.x; q < 2048; q += blockDim.x)
                if (ei32[2 * q + 1] != 0) local = 1;
            if (local) atomicOr(&nz, 1);
            __syncthreads();
            if (threadIdx.x == 0) g_is64 = nz ? 0 : 1;
        }
    } else {
        int b = blockIdx.x - nInitBlocks;   // 0..5
        const float* W = p.W[b];
        int K = p.K[b], N = p.N[b];
        for (int idx = threadIdx.x; idx < K * N; idx += blockDim.x) {
            int k = idx / N, n = idx % N;
            split_f16(W[idx], g_wth[b][n * K + k], g_wtl[b][n * K + k]);
        }
    }
}

// ================= fused: count + x->fp16 =================
__global__ void k_count_convx(const int* __restrict__ ei32, const float* __restrict__ x,
                              __half* __restrict__ xh, int nCountBlocks) {
    if ((int)blockIdx.x < nCountBlocks) {
        int e = blockIdx.x * blockDim.x + threadIdx.x;
        if (e < N_EDGES) {
            int d = g_is64 ? ei32[2 * (N_EDGES + e)] : ei32[N_EDGES + e];
            atomicAdd(&g_edeg[d], 1);
        }
    } else {
        int i = (blockIdx.x - nCountBlocks) * blockDim.x + threadIdx.x;  // 800000 total
        const float4* xp = reinterpret_cast<const float4*>(x) + 2 * (size_t)i;
        float4 a = xp[0], b = xp[1];
        __half2 h[4];
        h[0] = {__float2half_rn(a.x), __float2half_rn(a.y)};
        h[1] = {__float2half_rn(a.z), __float2half_rn(a.w)};
        h[2] = {__float2half_rn(b.x), __float2half_rn(b.y)};
        h[3] = {__float2half_rn(b.z), __float2half_rn(b.w)};
        reinterpret_cast<uint4*>(xh)[i] = *reinterpret_cast<uint4*>(h);
    }
}

__global__ void k_scan_dinv() {
    __shared__ int part[1024];
    const int t = threadIdx.x;
    const int CH = (N_NODES + 1023) / 1024;
    int start = t * CH;
    int s = 0;
    for (int i = 0; i < CH; i++) { int idx = start + i; if (idx < N_NODES) s += g_edeg[idx]; }
    part[t] = s;
    __syncthreads();
    for (int off = 1; off < 1024; off <<= 1) {
        int v = (t >= off) ? part[t - off] : 0;
        __syncthreads();
        part[t] += v;
        __syncthreads();
    }
    int run = (t == 0) ? 0 : part[t - 1];
    for (int i = 0; i < CH; i++) {
        int idx = start + i;
        if (idx < N_NODES) {
            g_rowptr[idx] = run;
            g_cursor[idx] = run;
            g_dinv[idx] = rsqrtf((float)(g_edeg[idx] + 1));
            run += g_edeg[idx];
        }
    }
    if (t == 1023) g_rowptr[N_NODES] = run;
}

__global__ void k_fill(const int* __restrict__ ei32) {
    int e = blockIdx.x * blockDim.x + threadIdx.x;
    if (e < N_EDGES) {
        int s, d;
        if (g_is64) { s = ei32[2 * e]; d = ei32[2 * (N_EDGES + e)]; }
        else        { s = ei32[e];     d = ei32[N_EDGES + e]; }
        int p = atomicAdd(&g_cursor[d], 1);
        g_col[p] = s;
        g_wedge[p] = g_dinv[s] * g_dinv[d];
    }
}

// ================= warp-per-node aggregation (fp16 gather) =================
__global__ __launch_bounds__(256, 8) void k_agg128(const __half* __restrict__ in,
                                                   __half* __restrict__ oh) {
    const int warp = threadIdx.x >> 5, lane = threadIdx.x & 31;
    const int n = blockIdx.x * 8 + warp;
    const int c4 = lane * 4;
    float dn = g_dinv[n];
    float acc0, acc1, acc2, acc3;
    {
        uint2 sv = *reinterpret_cast<const uint2*>(in + (size_t)n * 128 + c4);
        __half2 s0 = *reinterpret_cast<__half2*>(&sv.x);
        __half2 s1 = *reinterpret_cast<__half2*>(&sv.y);
        float w = dn * dn;
        acc0 = w * __half2float(s0.x); acc1 = w * __half2float(s0.y);
        acc2 = w * __half2float(s1.x); acc3 = w * __half2float(s1.y);
    }
    const int beg = g_rowptr[n], end = g_rowptr[n + 1];
    for (int base = beg; base < end; base += 32) {
        int cnt = end - base; if (cnt > 32) cnt = 32;
        int   col = 0; float wt = 0.0f;
        if (lane < cnt) { col = g_col[base + lane]; wt = g_wedge[base + lane]; }
        for (int j = 0; j < cnt; j++) {
            int   idx = __shfl_sync(0xFFFFFFFFu, col, j);
            float ww  = __shfl_sync(0xFFFFFFFFu, wt,  j);
            uint2 gv = *reinterpret_cast<const uint2*>(in + (size_t)idx * 128 + c4);
            __half2 g0 = *reinterpret_cast<__half2*>(&gv.x);
            __half2 g1 = *reinterpret_cast<__half2*>(&gv.y);
            acc0 += ww * __half2float(g0.x); acc1 += ww * __half2float(g0.y);
            acc2 += ww * __half2float(g1.x); acc3 += ww * __half2float(g1.y);
        }
    }
    __half2 o0 = {__float2half_rn(acc0), __float2half_rn(acc1)};
    __half2 o1 = {__float2half_rn(acc2), __float2half_rn(acc3)};
    *reinterpret_cast<uint2*>(oh + (size_t)n * 128 + c4) = make_uint2(
        *reinterpret_cast<uint32_t*>(&o0), *reinterpret_cast<uint32_t*>(&o1));
}

__global__ __launch_bounds__(256, 8) void k_agg256(const __half* __restrict__ in,
                                                   __half* __restrict__ oh) {
    const int warp = threadIdx.x >> 5, lane = threadIdx.x & 31;
    const int n = blockIdx.x * 8 + warp;
    const int c8 = lane * 8;
    float dn = g_dinv[n];
    float acc[8];
    {
        uint4 sv = *reinterpret_cast<const uint4*>(in + (size_t)n * 256 + c8);
        const __half2* sh = reinterpret_cast<const __half2*>(&sv);
        float w = dn * dn;
#pragma unroll
        for (int q = 0; q < 4; q++) {
            acc[2 * q]     = w * __half2float(sh[q].x);
            acc[2 * q + 1] = w * __half2float(sh[q].y);
        }
    }
    const int beg = g_rowptr[n], end = g_rowptr[n + 1];
    for (int base = beg; base < end; base += 32) {
        int cnt = end - base; if (cnt > 32) cnt = 32;
        int   col = 0; float wt = 0.0f;
        if (lane < cnt) { col = g_col[base + lane]; wt = g_wedge[base + lane]; }
        for (int j = 0; j < cnt; j++) {
            int   idx = __shfl_sync(0xFFFFFFFFu, col, j);
            float ww  = __shfl_sync(0xFFFFFFFFu, wt,  j);
            uint4 gv = *reinterpret_cast<const uint4*>(in + (size_t)idx * 256 + c8);
            const __half2* gh = reinterpret_cast<const __half2*>(&gv);
#pragma unroll
            for (int q = 0; q < 4; q++) {
                acc[2 * q]     += ww * __half2float(gh[q].x);
                acc[2 * q + 1] += ww * __half2float(gh[q].y);
            }
        }
    }
    __half2 hv[4];
#pragma unroll
    for (int q = 0; q < 4; q++)
        hv[q] = {__float2half_rn(acc[2 * q]), __float2half_rn(acc[2 * q + 1])};
    *reinterpret_cast<uint4*>(oh + (size_t)n * 256 + c8) = *reinterpret_cast<uint4*>(hv);
}

// ================= fp16 2-pass mma.sync GEMM =================
struct MJobs {
    const __half* A[3];
    const __half* Bh[3];
    const __half* Bl[3];
    const float*  bias[3];
    float*        C[3];
    __half*       Ch[3];
    int           lda[3];
    int           ldc[3];
    int           split[3];
};

template <int THREADS, int BM, int NN, int KK>
__global__ __launch_bounds__(THREADS, 2) void k_mma(MJobs jobs, int do_relu) {
    extern __shared__ __align__(16) unsigned char smem[];
    constexpr int NCH = KK / 8;
    constexpr int AB  = BM * KK * 2;
    constexpr int BB  = NN * KK * 2;
    constexpr int MWARPS = (THREADS == 512) ? 4 : 2;
    constexpr int MI  = BM / MWARPS / 16;
    constexpr int NI  = NN / 4 / 8;
    constexpr int KSTEPS = KK / 16;

    const int job = blockIdx.z;
    const int bm  = blockIdx.y * BM;
    const int tid = threadIdx.x;
    const int lane = tid & 31, warp = tid >> 5;
    const int wm = (warp >> 2) * (BM / MWARPS);
    const int wn = (warp & 3) * (NN / 4);

    const __half* A = jobs.A[job];
    const int lda = jobs.lda[job];

    {
        const int ldach = lda / 8;
        uint4* s = reinterpret_cast<uint4*>(smem);
        for (int idx = tid; idx < BM * NCH; idx += THREADS) {
            int r = idx / NCH, cc = idx % NCH;
            long gr = bm + r; if (gr >= N_NODES) gr = N_NODES - 1;
            int sp = r * NCH + (cc ^ (r & 7));
            s[sp] = reinterpret_cast<const uint4*>(A)[gr * ldach + cc];
        }
        const uint4* bh = reinterpret_cast<const uint4*>(jobs.Bh[job]);
        const uint4* bl = reinterpret_cast<const uint4*>(jobs.Bl[job]);
        uint4* sb = reinterpret_cast<uint4*>(smem + AB);
        for (int idx = tid; idx < NN * NCH; idx += THREADS) {
            int r = idx / NCH, cc = idx % NCH;
            int sp = r * NCH + (cc ^ (r & 7));
            sb[sp]           = bh[idx];
            sb[sp + BB / 16] = bl[idx];
        }
    }
    __syncthreads();

    const uint32_t sbase = smem_u32(smem);
    const int group = lane >> 3, within = lane & 7;
    const int kaddA = group >> 1;
    uint32_t abyte[MI]; int rx[MI];
    {
        int mrow = wm + (group & 1) * 8 + within;
#pragma unroll
        for (int mi = 0; mi < MI; mi++) {
            int r = mrow + mi * 16;
            abyte[mi] = (uint32_t)(r * NCH) << 4;
            rx[mi] = r & 7;
        }
    }
    const int laneB = lane & 15;
    const int kaddB = laneB >> 3, withinB = laneB & 7;
    uint32_t bbyte[NI]; int nx[NI];
#pragma unroll
    for (int ni = 0; ni < NI; ni++) {
        int r = wn + ni * 8 + withinB;
        bbyte[ni] = (uint32_t)(r * NCH) << 4;
        nx[ni] = r & 7;
    }

    float acc[MI][NI][4];
#pragma unroll
    for (int mi = 0; mi < MI; mi++)
#pragma unroll
        for (int ni = 0; ni < NI; ni++)
#pragma unroll
            for (int q = 0; q < 4; q++) acc[mi][ni][q] = 0.0f;

#pragma unroll 1
    for (int pass = 0; pass < 2; pass++) {
        const uint32_t aoff = sbase;
        const uint32_t boff = sbase + AB + pass * BB;
#pragma unroll
        for (int s = 0; s < KSTEPS; s++) {
            const int kc = s * 2;
            uint32_t bf[NI][2];
#pragma unroll
            for (int ni = 0; ni < NI; ni++)
                ldsm_x2(bf[ni], boff + bbyte[ni] + ((uint32_t)((kc + kaddB) ^ nx[ni]) << 4));
#pragma unroll
            for (int mi = 0; mi < MI; mi++) {
                uint32_t af[4];
                ldsm_x4(af, aoff + abyte[mi] + ((uint32_t)((kc + kaddA) ^ rx[mi]) << 4));
#pragma unroll
                for (int ni = 0; ni < NI; ni++)
                    mma_f16(acc[mi][ni], af, bf[ni]);
            }
        }
    }

    const float* bias = jobs.bias[job];
    float* C = jobs.C[job];
    __half* Ch = jobs.Ch[job];
    const int ldc = jobs.ldc[job];
    const int splt = jobs.split[job];
    const int g = lane >> 2, tc = lane & 3;
#pragma unroll
    for (int mi = 0; mi < MI; mi++) {
#pragma unroll
        for (int ni = 0; ni < NI; ni++) {
            int n0 = wn + ni * 8 + tc * 2;
            float b0 = bias[n0], b1 = bias[n0 + 1];
            int m0 = bm + wm + mi * 16 + g;
            float v0 = acc[mi][ni][0] + b0, v1 = acc[mi][ni][1] + b1;
            float v2 = acc[mi][ni][2] + b0, v3 = acc[mi][ni][3] + b1;
            if (do_relu) {
                v0 = fmaxf(v0, 0.0f); v1 = fmaxf(v1, 0.0f);
                v2 = fmaxf(v2, 0.0f); v3 = fmaxf(v3, 0.0f);
            }
            if (splt) {
                if (m0 < N_NODES)
                    *reinterpret_cast<__half2*>(Ch + (size_t)m0 * ldc + n0) =
                        __half2{__float2half_rn(v0), __float2half_rn(v1)};
                if (m0 + 8 < N_NODES)
                    *reinterpret_cast<__half2*>(Ch + (size_t)(m0 + 8) * ldc + n0) =
                        __half2{__float2half_rn(v2), __float2half_rn(v3)};
            } else {
                if (m0 < N_NODES)
                    *reinterpret_cast<float2*>(C + (size_t)m0 * ldc + n0) = make_float2(v0, v1);
                if (m0 + 8 < N_NODES)
                    *reinterpret_cast<float2*>(C + (size_t)(m0 + 8) * ldc + n0) = make_float2(v2, v3);
            }
        }
    }
}

// ================= attention fusion (fp16 h1/h2) =================
__global__ void k_attn(const float* __restrict__ watt, const float* __restrict__ batt) {
    const int half = threadIdx.x >> 7;
    const int c = threadIdx.x & 127;
    const int n = blockIdx.x * 2 + half;
    float h1v = __half2float(g_h1[n * 128 + c]);
    float h2v = __half2float(g_h2[n * 128 + c]);
    float wa = watt[c];
    float p1 = h1v * wa;
    float p2 = h2v * wa;
#pragma unroll
    for (int o = 16; o > 0; o >>= 1) {
        p1 += __shfl_down_sync(0xFFFFFFFFu, p1, o);
        p2 += __shfl_down_sync(0xFFFFFFFFu, p2, o);
    }
    __shared__ float s1[8], s2[8];
    __shared__ float a1s[2];
    int w = threadIdx.x >> 5;
    if ((threadIdx.x & 31) == 0) { s1[w] = p1; s2[w] = p2; }
    __syncthreads();
    if (c == 0) {
        int b = half * 4;
        float S1 = s1[b] + s1[b+1] + s1[b+2] + s1[b+3] + batt[0];
        float S2 = s2[b] + s2[b+1] + s2[b+2] + s2[b+3] + batt[0];
        a1s[half] = 1.0f / (1.0f + expf(S2 - S1));
    }
    __syncthreads();
    float a1 = a1s[half];
    float v = a1 * h1v + (1.0f - a1) * h2v;
    g_comb[n * 256 + 128 + c] = __float2half_rn(v);
}

// ================= launch =================
extern "C" void kernel_launch(void* const* d_in, const int* in_sizes, int n_in,
                              void* d_out, int out_size) {
    const float* x    = (const float*)d_in[0];
    const int*   ei32 = (const int*)d_in[1];
    const float* W_s1 = (const float*)d_in[2];
    const float* b_s1 = (const float*)d_in[3];
    const float* W_s2 = (const float*)d_in[4];
    const float* b_s2 = (const float*)d_in[5];
    const float* W_m1 = (const float*)d_in[6];
    const float* b_m1 = (const float*)d_in[7];
    const float* W_m21 = (const float*)d_in[8];
    const float* b_m21 = (const float*)d_in[9];
    const float* W_m22 = (const float*)d_in[10];
    const float* b_m22 = (const float*)d_in[11];
    const float* W_att = (const float*)d_in[12];
    const float* b_att = (const float*)d_in[13];
    const float* W_fc  = (const float*)d_in[14];
    const float* b_fc  = (const float*)d_in[15];
    float* out = (float*)d_out;

    __half *h1, *h2, *xh, *bufA, *aggx, *agg2, *comb, *wth, *wtl;
    cudaGetSymbolAddress((void**)&h1, g_h1);
    cudaGetSymbolAddress((void**)&h2, g_h2);
    cudaGetSymbolAddress((void**)&xh, g_xh);
    cudaGetSymbolAddress((void**)&bufA, g_bufA);
    cudaGetSymbolAddress((void**)&aggx, g_aggx);
    cudaGetSymbolAddress((void**)&agg2, g_agg2);
    cudaGetSymbolAddress((void**)&comb, g_comb);
    cudaGetSymbolAddress((void**)&wth, g_wth);
    cudaGetSymbolAddress((void**)&wtl, g_wtl);

    const int SM_L  = 128 * 128 * 2 + 2 * (128 * 128 * 2);  // 98304, occ 2, 512 thr
    const int SM_FC = 64 * 256 * 2 + 2 * (64 * 256 * 2);    // 98304, occ 2, 256 thr
    static bool attr_done = false;
    if (!attr_done) {
        cudaFuncSetAttribute(k_mma<512, 128, 128, 128>, cudaFuncAttributeMaxDynamicSharedMemorySize, SM_L);
        cudaFuncSetAttribute(k_mma<256, 64, 64, 256>,   cudaFuncAttributeMaxDynamicSharedMemorySize, SM_FC);
        attr_done = true;
    }

    const int TB = 256;
    const int initBlocks  = (N_NODES + TB - 1) / TB;   // 196
    const int countBlocks = (N_EDGES + TB - 1) / TB;   // 3125
    const int convxBlocks = (N_NODES * 128 / 8) / TB;  // 3125

    PrepB p;
    p.W[0] = W_s1;  p.K[0] = 128; p.N[0] = 128;
    p.W[1] = W_m21; p.K[1] = 128; p.N[1] = 128;
    p.W[2] = W_m1;  p.K[2] = 128; p.N[2] = 128;
    p.W[3] = W_s2;  p.K[3] = 128; p.N[3] = 128;
    p.W[4] = W_m22; p.K[4] = 128; p.N[4] = 128;
    p.W[5] = W_fc;  p.K[5] = 256; p.N[5] = 64;

    k_detect_init_prep<<<initBlocks + 6, TB>>>(ei32, p, initBlocks);
    k_count_convx<<<countBlocks + convxBlocks, TB>>>(ei32, x, xh, countBlocks);
    k_scan_dinv<<<1, 1024>>>();
    k_fill<<<countBlocks, TB>>>(ei32);

    k_agg128<<<N_NODES / 8, 256>>>(xh, aggx);

    const int MT128 = (N_NODES + 127) / 128;  // 391
    const int MT64  = (N_NODES + 63) / 64;    // 782

    {
        MJobs j = {};
        for (int q = 0; q < 3; q++) { j.A[q] = aggx; j.lda[q] = 128; }
        j.Bh[0] = wth + 0 * 16384; j.Bl[0] = wtl + 0 * 16384; j.bias[0] = b_s1;
        j.Ch[0] = bufA;       j.ldc[0] = 256; j.split[0] = 1;
        j.Bh[1] = wth + 1 * 16384; j.Bl[1] = wtl + 1 * 16384; j.bias[1] = b_m21;
        j.Ch[1] = bufA + 128; j.ldc[1] = 256; j.split[1] = 1;
        j.Bh[2] = wth + 2 * 16384; j.Bl[2] = wtl + 2 * 16384; j.bias[2] = b_m1;
        j.Ch[2] = h1; j.ldc[2] = 128; j.split[2] = 1;
        k_mma<512, 128, 128, 128><<<dim3(1, MT128, 3), 512, SM_L>>>(j, 1);
    }

    k_agg256<<<N_NODES / 8, 256>>>(bufA, agg2);

    {
        MJobs j = {};
        j.A[0] = agg2;       j.lda[0] = 256;
        j.A[1] = agg2 + 128; j.lda[1] = 256;
        j.A[2] = j.A[0];     j.lda[2] = 256;
        j.Bh[0] = wth + 3 * 16384; j.Bl[0] = wtl + 3 * 16384; j.bias[0] = b_s2;
        j.Ch[0] = comb; j.ldc[0] = 256; j.split[0] = 1;
        j.Bh[1] = wth + 4 * 16384; j.Bl[1] = wtl + 4 * 16384; j.bias[1] = b_m22;
        j.Ch[1] = h2; j.ldc[1] = 128; j.split[1] = 1;
        j.Bh[2] = j.Bh[0]; j.Bl[2] = j.Bl[0]; j.bias[2] = j.bias[0];
        j.Ch[2] = j.Ch[0]; j.ldc[2] = j.ldc[0]; j.split[2] = 1;
        k_mma<512, 128, 128, 128><<<dim3(1, MT128, 2), 512, SM_L>>>(j, 1);
    }

    k_attn<<<N_NODES / 2, 256>>>(W_att, b_att);

    {
        MJobs j = {};
        for (int q = 0; q < 3; q++) {
            j.A[q] = comb; j.lda[q] = 256;
            j.Bh[q] = wth + 5 * 16384; j.Bl[q] = wtl + 5 * 16384;
            j.bias[q] = b_fc; j.C[q] = out; j.ldc[q] = 64; j.split[q] = 0;
        }
        k_mma<256, 64, 64, 256><<<dim3(1, MT64, 1), 256, SM_FC>>>(j, 0);
    }

    (void)in_sizes; (void)n_in; (void)out_size;
}